// round 4
// baseline (speedup 1.0000x reference)
#include <cuda_runtime.h>
#include <math.h>

#define B  32
#define N  128
#define E  16384
#define D  72
#define H  72
#define O  72
#define A  4
#define EPS 1e-5f
#define BE (B*E)            // 524288
#define BNODES (B*N)        // 4096

#define X_OUT_OFF (B*N*O)                 // 294912
#define M_OUT_OFF (X_OUT_OFF + B*N*4)     // 311296

#define ZROW 10               // staging row stride (floats): 8 edges + 2 pad

typedef unsigned long long ull;

// ---------------- device scratch (no allocations allowed) ----------------
__device__ float g_Yi[BNODES*H];     // h @ We1[0:72]
__device__ float g_Yj[BNODES*H];     // h @ We1[72:144]
__device__ float g_magg[BNODES*H];
__device__ float g_stats1[2*H];
__device__ float g_stats2[2*H];
__device__ float g_bn1[2*H];         // scale, shift
__device__ float g_bn2[2*H];
__device__ float g_z2[BNODES*H];
// CSR sort results
__device__ int    g_off[BNODES];
__device__ int    g_deg[BNODES];
__device__ int2   g_se[BE];          // (ej, original edge id) at sorted position
__device__ float2 g_nd[BE];          // (norms, dots) at sorted position

// ---------------- f32x2 helpers ----------------
__device__ __forceinline__ ull dup2(float w){
    ull r; asm("mov.b64 %0, {%1,%1};" : "=l"(r) : "f"(w)); return r;
}
__device__ __forceinline__ void fma2(ull& c, ull a, ull b){
    asm("fma.rn.f32x2 %0, %1, %2, %0;" : "+l"(c) : "l"(a), "l"(b));
}
__device__ __forceinline__ float2 unpk(ull v){
    float2 r; asm("mov.b64 {%0,%1}, %2;" : "=f"(r.x), "=f"(r.y) : "l"(v)); return r;
}

__device__ __forceinline__ float psi_f(float p){
    return copysignf(log1pf(fabsf(p)), p);
}

// ---------------- K0: zero stat accumulators ----------------
__global__ void k0_zero() {
    int i = threadIdx.x;
    if (i < 2*H) { g_stats1[i]=0.f; g_stats2[i]=0.f; }
}

// ---------------- KS: counting sort edges by ei (per batch) ----------------
__global__ void ksort(const int* __restrict__ ei, const int* __restrict__ ej) {
    __shared__ int cnt[N];
    __shared__ int offs[N];
    __shared__ int curs[N];
    const int b = blockIdx.x;
    const int tid = threadIdx.x;
    if (tid < N) cnt[tid] = 0;
    __syncthreads();
    for (int e = tid; e < E; e += 256) atomicAdd(&cnt[ei[b*E+e]], 1);
    __syncthreads();
    if (tid == 0){
        int s = 0;
        for (int n2 = 0; n2 < N; n2++){ offs[n2] = s; s += cnt[n2]; }
    }
    __syncthreads();
    if (tid < N){
        g_off[b*N+tid] = offs[tid];
        g_deg[b*N+tid] = cnt[tid];
        curs[tid] = offs[tid];
    }
    __syncthreads();
    for (int e = tid; e < E; e += 256){
        int n2 = ei[b*E+e];
        int p = atomicAdd(&curs[n2], 1);
        g_se[b*E+p] = make_int2(ej[b*E+e], e);
    }
}

// ---------------- K1a: Y factorization (per-node h @ We1 halves) ----------------
__global__ void k1a_yfac(const float* __restrict__ h, const float* __restrict__ We1) {
    const int tid = threadIdx.x;
    const int w = tid>>5, l = tid&31;
    const bool hi = (l<8);
    const int l2 = hi ? l+64 : l;
    const int n = blockIdx.x*8 + w;
    const int b = blockIdx.y;
    const int row = b*N + n;
    const float* hrow = h + row*D;
    float ai0=0.f, ai1=0.f, ai2=0.f, aj0=0.f, aj1=0.f, aj2=0.f;
    #pragma unroll 4
    for (int k=0;k<D;k++){
        float hv = __ldg(hrow+k);
        const float* wr  = We1 + k*H;
        const float* wr2 = We1 + (D+k)*H;
        ai0 += hv*wr[l];  ai1 += hv*wr[l+32];  ai2 += hv*wr[l2];
        aj0 += hv*wr2[l]; aj1 += hv*wr2[l+32]; aj2 += hv*wr2[l2];
    }
    float* yi = g_Yi + row*H;
    float* yj = g_Yj + row*H;
    yi[l]=ai0; yi[l+32]=ai1; if(hi) yi[l2]=ai2;
    yj[l]=aj0; yj[l+32]=aj1; if(hi) yj[l2]=aj2;
}

// ---------------- K1e: BN1 stats, lane-parallel psi + broadcast z loop ----------------
__global__ void k1e_stats(const float* __restrict__ x, const float* __restrict__ We1)
{
    extern __shared__ float sm[];
    float* Yjs = sm;                 // N*H = 9216
    float* xs  = Yjs + N*H;          // 512
    float* w144= xs + N*4;           // 72
    float* w145= w144 + H;           // 72
    float* red = w145 + H;           // 144
    float4* ebuf = (float4*)(red + 2*H);  // 8 warps * 32 recs * float4 = 4096 floats
    const int tid = threadIdx.x;
    const int b = blockIdx.y;
    {
        const float4* s = (const float4*)(g_Yj + b*N*H);
        float4* d = (float4*)Yjs;
        for (int i=tid;i<N*H/4;i+=256) d[i]=s[i];
        s = (const float4*)(x + b*N*4); d = (float4*)xs;
        for (int i=tid;i<N;i+=256) d[i]=s[i];
    }
    if (tid < H){ w144[tid]=We1[144*H+tid]; w145[tid]=We1[145*H+tid]; }
    for (int i=tid;i<2*H;i+=256) red[i]=0.f;
    __syncthreads();

    const int w = tid>>5, l = tid&31;
    const bool hi = (l<8);
    const int l2 = hi ? l+64 : l;
    const int n = blockIdx.x*8 + w;
    const int row = b*N + n;
    const int deg = g_deg[row];
    const long base = (long)b*E + g_off[row];
    float4* ebw = ebuf + w*32;

    const float yin0 = g_Yi[row*H+l], yin1 = g_Yi[row*H+l+32], yin2 = g_Yi[row*H+l2];
    const float xi0 = xs[n*4+0], xi1 = xs[n*4+1], xi2 = xs[n*4+2], xi3 = xs[n*4+3];
    const float w144l=w144[l], w144m=w144[l+32], w144h=w144[l2];
    const float w145l=w145[l], w145m=w145[l+32], w145h=w145[l2];

    float s0=0.f,s1=0.f,s2=0.f,q0=0.f,q1=0.f,q2=0.f;
    const float4* xsv = (const float4*)xs;

    for (int s=0; s<deg; s+=32){
        const int g = min(32, deg-s);
        // phase 1: lane-parallel psi (lane l owns edge s+l)
        {
            const bool v = (l < g);
            int jt = v ? __ldg(&g_se[base+s+l]).x : n;
            float4 xj = xsv[jt];
            float d0=xi0-xj.x, d1=xi1-xj.y, d2=xi2-xj.z, d3=xi3-xj.w;
            float nrm = psi_f(d0*d0 - d1*d1 - d2*d2 - d3*d3);
            float dts = psi_f(xi0*xj.x - xi1*xj.y - xi2*xj.z - xi3*xj.w);
            if (v) g_nd[base+s+l] = make_float2(nrm, dts);
            ebw[l] = make_float4(__int_as_float(jt), nrm, dts, 0.f);
        }
        __syncwarp();
        // phase 2: z + stats (LDS.128 broadcasts)
        for (int t=0; t<g; t++){
            float4 r = ebw[t];
            int jt = __float_as_int(r.x);
            const float* yj = Yjs + jt*H;
            float z0 = yin0 + yj[l]    + r.y*w144l + r.z*w145l;
            float z1 = yin1 + yj[l+32] + r.y*w144m + r.z*w145m;
            s0+=z0; q0=fmaf(z0,z0,q0); s1+=z1; q1=fmaf(z1,z1,q1);
            if (hi){
                float z2v = yin2 + yj[l2] + r.y*w144h + r.z*w145h;
                s2+=z2v; q2=fmaf(z2v,z2v,q2);
            }
        }
        __syncwarp();
    }
    atomicAdd(&red[l], s0);    atomicAdd(&red[H+l], q0);
    atomicAdd(&red[l+32], s1); atomicAdd(&red[H+l+32], q1);
    if (hi){ atomicAdd(&red[l2], s2); atomicAdd(&red[H+l2], q2); }
    __syncthreads();
    if (tid < 2*H) atomicAdd(&g_stats1[tid], red[tid]);
}

// ---------------- BN finalize (shared for bn1/bn2) ----------------
__global__ void k_bnfin(const float* __restrict__ gamma, const float* __restrict__ beta,
                        float cnt, int which)
{
    int j = threadIdx.x; if (j>=H) return;
    const float* st = which ? g_stats2 : g_stats1;
    float* bn = which ? g_bn2 : g_bn1;
    float mu  = st[j]/cnt;
    float var = st[H+j]/cnt - mu*mu;
    float sc  = gamma[j]*rsqrtf(var+EPS);
    bn[j]   = sc;
    bn[H+j] = beta[j] - mu*sc;
}

// ---------------- K2: fused edge pipeline, warp-per-node, 3 blocks/SM ----------------
__global__ void __launch_bounds__(256,3)
k2_edge(const float* __restrict__ x,
        const float* __restrict__ We1,
        const float* __restrict__ We2, const float* __restrict__ be2,
        const float* __restrict__ Wm,  const float* __restrict__ bm,
        const float* __restrict__ Wx1, const float* __restrict__ bx1,
        const float* __restrict__ Wx2,
        float* __restrict__ out)
{
    extern __shared__ float sm[];
    float* xs    = sm;                // 512
    float* We2s  = xs + N*4;          // 5184
    float* Wx1s  = We2s + H*H;        // 5184
    float* Wms   = Wx1s + H*H;        // 72
    float* Wx2s  = Wms + H;           // 72
    float* be2s  = Wx2s + H;          // 72
    float* bx1s  = be2s + H;          // 72
    float* sc1   = bx1s + H;          // 72
    float* sh1   = sc1 + H;           // 72
    float* w144  = sh1 + H;           // 72
    float* w145  = w144 + H;          // 72
    float* stg   = w145 + H;          // 8*H*ZROW = 5760 (shared za/ms staging)

    const int tid = threadIdx.x;
    const int b = blockIdx.y;
    {
        const float4* s = (const float4*)(x + b*N*4);
        float4* d = (float4*)xs;
        for (int i=tid;i<N;i+=256) d[i]=s[i];
    }
    for (int i=tid;i<H*H;i+=256){ We2s[i]=We2[i]; Wx1s[i]=Wx1[i]; }
    if (tid < H){
        Wms[tid]=Wm[tid]; Wx2s[tid]=Wx2[tid]; be2s[tid]=be2[tid]; bx1s[tid]=bx1[tid];
        sc1[tid]=g_bn1[tid]; sh1[tid]=g_bn1[H+tid];
        w144[tid]=We1[144*H+tid]; w145[tid]=We1[145*H+tid];
    }
    __syncthreads();

    const int w = tid>>5, l = tid&31;
    const bool hi = (l<8);
    const int l2 = hi ? l+64 : l;
    float* zaw = stg + w*H*ZROW;      // reused for za AND ms (disjoint lifetimes)
    const float bmv = __ldg(bm);

    const int n = blockIdx.x*8 + w;
    const int row = b*N + n;
    const int deg = g_deg[row];
    const long base = (long)b*E + g_off[row];
    float* mout = out + M_OUT_OFF + (size_t)b*E*H;
    const float* gYjb = g_Yj + (size_t)b*N*H;

    const float yin0 = g_Yi[row*H+l], yin1 = g_Yi[row*H+l+32], yin2 = g_Yi[row*H+l2];
    const float xil = (l<4) ? xs[n*4+l] : 0.f;

    float mg0=0.f, mg1=0.f, mg2=0.f;   // magg accumulators (registers)
    float axv=0.f;                      // x-agg accumulator (lanes 0..3)

    for (int s=0; s<deg; s+=8){
        const int g = min(8, deg-s);
        int jj[8], eid[8]; float nrm[8], dts[8];
        #pragma unroll
        for (int t=0;t<8;t++){
            if (t<g){
                int2 se = __ldg(&g_se[base+s+t]);
                jj[t]=se.x; eid[t]=se.y;
                float2 nd = __ldg(&g_nd[base+s+t]);
                nrm[t]=nd.x; dts[t]=nd.y;
            } else { jj[t]=n; eid[t]=0; nrm[t]=0.f; dts[t]=0.f; }
        }
        // stage z (BN1 + ReLU), pad slots -> 0; yj gathered from global (L2-hot)
        {
            const float w144l=w144[l], w144m=w144[l+32], w144h=w144[l2];
            const float w145l=w145[l], w145m=w145[l+32], w145h=w145[l2];
            const float sc1l=sc1[l], sc1m=sc1[l+32], sc1h=sc1[l2];
            const float sh1l=sh1[l], sh1m=sh1[l+32], sh1h=sh1[l2];
            #pragma unroll
            for (int t=0;t<8;t++){
                const float* yj = gYjb + (size_t)jj[t]*H;
                float yj0=__ldg(yj+l), yj1=__ldg(yj+l+32), yj2=__ldg(yj+l2);
                float z0 = yin0 + yj0 + nrm[t]*w144l + dts[t]*w145l;
                float z1 = yin1 + yj1 + nrm[t]*w144m + dts[t]*w145m;
                zaw[l*ZROW+t]      = (t<g) ? fmaxf(z0*sc1l+sh1l, 0.f) : 0.f;
                zaw[(l+32)*ZROW+t] = (t<g) ? fmaxf(z1*sc1m+sh1m, 0.f) : 0.f;
                if (hi){
                    float z2v = yin2 + yj2 + nrm[t]*w144h + dts[t]*w145h;
                    zaw[l2*ZROW+t] = (t<g) ? fmaxf(z2v*sc1h+sh1h, 0.f) : 0.f;
                }
            }
        }
        __syncwarp();
        // GEMM1: relu(za @ We2 + be2)   (f32x2, edge pairs packed)
        ull a0[4], a1[4], a2[4];
        {
            ull be2p0=dup2(be2s[l]), be2p1=dup2(be2s[l+32]), be2p2=dup2(be2s[l2]);
            #pragma unroll
            for (int p=0;p<4;p++){ a0[p]=be2p0; a1[p]=be2p1; a2[p]=be2p2; }
        }
        #pragma unroll 4
        for (int k=0;k<H;k++){
            const ull* zr = (const ull*)(zaw + k*ZROW);
            ull zp0=zr[0], zp1=zr[1], zp2=zr[2], zp3=zr[3];
            ull wd0=dup2(We2s[k*H+l]), wd1=dup2(We2s[k*H+l+32]), wd2=dup2(We2s[k*H+l2]);
            fma2(a0[0],zp0,wd0); fma2(a0[1],zp1,wd0); fma2(a0[2],zp2,wd0); fma2(a0[3],zp3,wd0);
            fma2(a1[0],zp0,wd1); fma2(a1[1],zp1,wd1); fma2(a1[2],zp2,wd1); fma2(a1[3],zp3,wd1);
            fma2(a2[0],zp0,wd2); fma2(a2[1],zp1,wd2); fma2(a2[2],zp2,wd2); fma2(a2[3],zp3,wd2);
        }
        float m0[8], m1[8], m2[8];
        #pragma unroll
        for (int p=0;p<4;p++){
            float2 u0=unpk(a0[p]), u1=unpk(a1[p]), u2=unpk(a2[p]);
            m0[2*p]=fmaxf(u0.x,0.f); m0[2*p+1]=fmaxf(u0.y,0.f);
            m1[2*p]=fmaxf(u1.x,0.f); m1[2*p+1]=fmaxf(u1.y,0.f);
            m2[2*p]=fmaxf(u2.x,0.f); m2[2*p+1]=fmaxf(u2.y,0.f);
        }
        // sigmoid gate: m = mp * sigmoid(mp @ Wm + bm)
        float gs[8];
        {
            const float wm0=Wms[l], wm1=Wms[l+32], wm2=Wms[l2];
            #pragma unroll
            for (int t=0;t<8;t++){
                float p = m0[t]*wm0 + m1[t]*wm1;
                if (hi) p += m2[t]*wm2;
                #pragma unroll
                for (int off=16; off>0; off>>=1) p += __shfl_xor_sync(0xffffffffu, p, off);
                gs[t] = 1.f/(1.f+expf(-(p+bmv)));
            }
        }
        __syncwarp();
        #pragma unroll
        for (int t=0;t<8;t++){
            float v0=m0[t]*gs[t], v1=m1[t]*gs[t], v2=m2[t]*gs[t];
            if (t<g){
                size_t mrow = (size_t)eid[t]*H;
                mout[mrow + l] = v0;
                mout[mrow + l + 32] = v1;
                if (hi) mout[mrow + l2] = v2;
                mg0 += v0; mg1 += v1; mg2 += v2;
            }
            // stage m for GEMM2 (reuse staging buffer)
            zaw[l*ZROW+t]=v0; zaw[(l+32)*ZROW+t]=v1; if(hi) zaw[l2*ZROW+t]=v2;
        }
        __syncwarp();
        // GEMM2: relu(m @ Wx1 + bx1) @ Wx2 -> scalar gate per edge (f32x2)
        ull t0[4], t1[4], t2[4];
        {
            ull bx1p0=dup2(bx1s[l]), bx1p1=dup2(bx1s[l+32]), bx1p2=dup2(bx1s[l2]);
            #pragma unroll
            for (int p=0;p<4;p++){ t0[p]=bx1p0; t1[p]=bx1p1; t2[p]=bx1p2; }
        }
        #pragma unroll 4
        for (int k=0;k<H;k++){
            const ull* zr = (const ull*)(zaw + k*ZROW);
            ull zp0=zr[0], zp1=zr[1], zp2=zr[2], zp3=zr[3];
            ull wd0=dup2(Wx1s[k*H+l]), wd1=dup2(Wx1s[k*H+l+32]), wd2=dup2(Wx1s[k*H+l2]);
            fma2(t0[0],zp0,wd0); fma2(t0[1],zp1,wd0); fma2(t0[2],zp2,wd0); fma2(t0[3],zp3,wd0);
            fma2(t1[0],zp0,wd1); fma2(t1[1],zp1,wd1); fma2(t1[2],zp2,wd1); fma2(t1[3],zp3,wd1);
            fma2(t2[0],zp0,wd2); fma2(t2[1],zp1,wd2); fma2(t2[2],zp2,wd2); fma2(t2[3],zp3,wd2);
        }
        float gate[8];
        {
            const float wx20=Wx2s[l], wx21=Wx2s[l+32], wx22=Wx2s[l2];
            #pragma unroll
            for (int p=0;p<4;p++){
                float2 u0=unpk(t0[p]), u1=unpk(t1[p]), u2=unpk(t2[p]);
                float pa = fmaxf(u0.x,0.f)*wx20 + fmaxf(u1.x,0.f)*wx21;
                float pb = fmaxf(u0.y,0.f)*wx20 + fmaxf(u1.y,0.f)*wx21;
                if (hi){ pa += fmaxf(u2.x,0.f)*wx22; pb += fmaxf(u2.y,0.f)*wx22; }
                gate[2*p]=pa; gate[2*p+1]=pb;
            }
        }
        #pragma unroll
        for (int t=0;t<8;t++){
            float p = gate[t];
            #pragma unroll
            for (int off=16; off>0; off>>=1) p += __shfl_xor_sync(0xffffffffu, p, off);
            gate[t] = p;
        }
        // x aggregation (clipped), register accumulation
        if (l < 4){
            #pragma unroll
            for (int t=0;t<8;t++){
                if (t<g){
                    float xd = xil - xs[jj[t]*4+l];
                    axv += fminf(fmaxf(xd*gate[t], -100.f), 100.f);
                }
            }
        }
    }
    // single plain stores per node — no atomics anywhere
    float* mgrow = g_magg + (size_t)row*H;
    mgrow[l]=mg0; mgrow[l+32]=mg1; if (hi) mgrow[l2]=mg2;
    if (l < 4){
        out[X_OUT_OFF + row*4 + l] = __ldg(&x[row*4+l]) + axv / fmaxf((float)deg, 1.f);
    }
}

// ---------------- K3a: node GEMM (hin @ Wh1 + bh1) + stats2 ----------------
__global__ void k3a_node(const float* __restrict__ h, const float* __restrict__ nattr,
                         const float* __restrict__ Wh1, const float* __restrict__ bh1)
{
    __shared__ float red[2*H];
    __shared__ float mrow_s[8][H];
    const int tid = threadIdx.x;
    const int w = tid>>5, l = tid&31;
    const bool hi = (l<8);
    const int l2 = hi ? l+64 : l;
    for (int i=tid;i<2*H;i+=256) red[i]=0.f;
    __syncthreads();
    const int n = blockIdx.x*8 + w;
    const int b = blockIdx.y;
    const int row = b*N + n;
    const float* mg = g_magg + (size_t)row*H;
    mrow_s[w][l]=mg[l]; mrow_s[w][l+32]=mg[l+32]; if (hi) mrow_s[w][l2]=mg[l2];
    __syncwarp();

    const float* hrow = h + row*D;
    const float* arow = nattr + row*A;
    float a0=bh1[l], a1=bh1[l+32], a2=bh1[l2];
    #pragma unroll 4
    for (int k=0;k<D;k++){
        float v = hrow[k];
        const float* wr = Wh1 + k*H;
        a0 += v*wr[l]; a1 += v*wr[l+32]; a2 += v*wr[l2];
    }
    #pragma unroll 4
    for (int k=0;k<H;k++){
        float v = mrow_s[w][k];
        const float* wr = Wh1 + (D+k)*H;
        a0 += v*wr[l]; a1 += v*wr[l+32]; a2 += v*wr[l2];
    }
    #pragma unroll
    for (int k=0;k<A;k++){
        float v = arow[k];
        const float* wr = Wh1 + (D+H+k)*H;
        a0 += v*wr[l]; a1 += v*wr[l+32]; a2 += v*wr[l2];
    }
    float* z2row = g_z2 + row*H;
    z2row[l]=a0; z2row[l+32]=a1; if (hi) z2row[l2]=a2;
    atomicAdd(&red[l], a0);    atomicAdd(&red[H+l], a0*a0);
    atomicAdd(&red[l+32], a1); atomicAdd(&red[H+l+32], a1*a1);
    if (hi){ atomicAdd(&red[l2], a2); atomicAdd(&red[H+l2], a2*a2); }
    __syncthreads();
    if (tid < 2*H) atomicAdd(&g_stats2[tid], red[tid]);
}

// ---------------- K3c: BN2+ReLU, @Wh2 + bh2, residual -> h_out ----------------
__global__ void k3c_node(const float* __restrict__ h, const float* __restrict__ Wh2,
                         const float* __restrict__ bh2, float* __restrict__ out)
{
    __shared__ float as_[8][H];
    const int tid=threadIdx.x, w=tid>>5, l=tid&31;
    const bool hi=(l<8);
    const int l2 = hi ? l+64 : l;
    const int n = blockIdx.x*8 + w;
    const int b = blockIdx.y;
    const int row = b*N + n;
    const float* z2row = g_z2 + row*H;
    as_[w][l]    = fmaxf(z2row[l]   *g_bn2[l]   +g_bn2[H+l],    0.f);
    as_[w][l+32] = fmaxf(z2row[l+32]*g_bn2[l+32]+g_bn2[H+l+32], 0.f);
    if (hi) as_[w][l2] = fmaxf(z2row[l2]*g_bn2[l2]+g_bn2[H+l2], 0.f);
    __syncwarp();
    float a0=bh2[l], a1=bh2[l+32], a2=bh2[l2];
    #pragma unroll 4
    for (int k=0;k<H;k++){
        float v = as_[w][k];
        const float* wr = Wh2 + k*O;
        a0 += v*wr[l]; a1 += v*wr[l+32]; a2 += v*wr[l2];
    }
    const float* hrow = h + row*D;
    out[row*O + l]      = hrow[l]    + a0;
    out[row*O + l + 32] = hrow[l+32] + a1;
    if (hi) out[row*O + l2] = hrow[l2] + a2;
}

// ---------------- host ----------------
extern "C" void kernel_launch(void* const* d_in, const int* in_sizes, int n_in,
                              void* d_out, int out_size) {
    const float* h     = (const float*)d_in[0];
    const float* x     = (const float*)d_in[1];
    const int*   ei    = (const int*)  d_in[2];
    const int*   ej    = (const int*)  d_in[3];
    const float* nattr = (const float*)d_in[4];
    const float* We1   = (const float*)d_in[5];
    const float* g1    = (const float*)d_in[6];
    const float* b1    = (const float*)d_in[7];
    const float* We2   = (const float*)d_in[8];
    const float* be2   = (const float*)d_in[9];
    const float* Wm    = (const float*)d_in[10];
    const float* bm    = (const float*)d_in[11];
    const float* Wx1   = (const float*)d_in[12];
    const float* bx1   = (const float*)d_in[13];
    const float* Wx2   = (const float*)d_in[14];
    const float* Wh1   = (const float*)d_in[15];
    const float* bh1   = (const float*)d_in[16];
    const float* gh    = (const float*)d_in[17];
    const float* bh    = (const float*)d_in[18];
    const float* Wh2   = (const float*)d_in[19];
    const float* bh2   = (const float*)d_in[20];
    float* out = (float*)d_out;

    const int SMEM1 = (N*H + N*4 + 2*H + 2*H + 8*32*4) * sizeof(float);      // 44,160 B
    const int SMEM2 = (N*4 + 2*H*H + 8*H + 8*H*ZROW) * sizeof(float);        // 68,864 B
    cudaFuncSetAttribute(k1e_stats, cudaFuncAttributeMaxDynamicSharedMemorySize, SMEM1);
    cudaFuncSetAttribute(k2_edge,   cudaFuncAttributeMaxDynamicSharedMemorySize, SMEM2);

    k0_zero<<<1, 256>>>();
    ksort<<<B, 256>>>(ei, ej);
    k1a_yfac<<<dim3(N/8, B), 256>>>(h, We1);
    k1e_stats<<<dim3(N/8, B), 256, SMEM1>>>(x, We1);
    k_bnfin<<<1, 128>>>(g1, b1, (float)BE, 0);
    k2_edge<<<dim3(N/8, B), 256, SMEM2>>>(x, We1, We2, be2, Wm, bm,
                                          Wx1, bx1, Wx2, out);
    k3a_node<<<dim3(N/8, B), 256>>>(h, nattr, Wh1, bh1);
    k_bnfin<<<1, 128>>>(gh, bh, (float)BNODES, 1);
    k3c_node<<<dim3(N/8, B), 256>>>(h, Wh2, bh2, out);
}

// round 5
// speedup vs baseline: 1.1241x; 1.1241x over previous
#include <cuda_runtime.h>
#include <math.h>

#define B  32
#define N  128
#define E  16384
#define D  72
#define H  72
#define O  72
#define A  4
#define EPS 1e-5f
#define BE (B*E)            // 524288
#define BNODES (B*N)        // 4096

#define X_OUT_OFF (B*N*O)                 // 294912
#define M_OUT_OFF (X_OUT_OFF + B*N*4)     // 311296

#define ZROW 10               // staging row stride (floats): 8 edges + 2 pad

typedef unsigned long long ull;

// ---------------- device scratch (no allocations allowed) ----------------
__device__ float g_Yi[BNODES*H];     // h @ We1[0:72]
__device__ float g_Yj[BNODES*H];     // h @ We1[72:144]
__device__ float g_magg[BNODES*H];
__device__ float g_stats1[2*H];
__device__ float g_stats2[2*H];
__device__ float g_z2[BNODES*H];
// CSR sort results
__device__ int    g_off[BNODES];
__device__ int    g_deg[BNODES];
__device__ int2   g_se[BE];          // (ej, original edge id) at sorted position
__device__ float2 g_nd[BE];          // (norms, dots) at sorted position

// ---------------- f32x2 helpers ----------------
__device__ __forceinline__ ull dup2(float w){
    ull r; asm("mov.b64 %0, {%1,%1};" : "=l"(r) : "f"(w)); return r;
}
__device__ __forceinline__ void fma2(ull& c, ull a, ull b){
    asm("fma.rn.f32x2 %0, %1, %2, %0;" : "+l"(c) : "l"(a), "l"(b));
}
__device__ __forceinline__ float2 unpk(ull v){
    float2 r; asm("mov.b64 {%0,%1}, %2;" : "=f"(r.x), "=f"(r.y) : "l"(v)); return r;
}

__device__ __forceinline__ float psi_f(float p){
    return copysignf(log1pf(fabsf(p)), p);
}

// ---------------- KS: counting sort edges by ei (per batch) + zero stats ----------------
__global__ void ksort(const int* __restrict__ ei, const int* __restrict__ ej) {
    __shared__ int cnt[N];
    __shared__ int offs[N];
    __shared__ int curs[N];
    const int b = blockIdx.x;
    const int tid = threadIdx.x;
    if (tid < 2*H){ g_stats1[tid]=0.f; g_stats2[tid]=0.f; }  // racy identical 0-writes: benign
    if (tid < N) cnt[tid] = 0;
    __syncthreads();
    for (int e = tid; e < E; e += 256) atomicAdd(&cnt[ei[b*E+e]], 1);
    __syncthreads();
    if (tid == 0){
        int s = 0;
        for (int n2 = 0; n2 < N; n2++){ offs[n2] = s; s += cnt[n2]; }
    }
    __syncthreads();
    if (tid < N){
        g_off[b*N+tid] = offs[tid];
        g_deg[b*N+tid] = cnt[tid];
        curs[tid] = offs[tid];
    }
    __syncthreads();
    for (int e = tid; e < E; e += 256){
        int n2 = ei[b*E+e];
        int p = atomicAdd(&curs[n2], 1);
        g_se[b*E+p] = make_int2(ej[b*E+e], e);
    }
}

// ---------------- K1a: Y factorization (per-node h @ We1 halves) ----------------
__global__ void k1a_yfac(const float* __restrict__ h, const float* __restrict__ We1) {
    const int tid = threadIdx.x;
    const int w = tid>>5, l = tid&31;
    const bool hi = (l<8);
    const int l2 = hi ? l+64 : l;
    const int n = blockIdx.x*8 + w;
    const int b = blockIdx.y;
    const int row = b*N + n;
    const float* hrow = h + row*D;
    float ai0=0.f, ai1=0.f, ai2=0.f, aj0=0.f, aj1=0.f, aj2=0.f;
    #pragma unroll 4
    for (int k=0;k<D;k++){
        float hv = __ldg(hrow+k);
        const float* wr  = We1 + k*H;
        const float* wr2 = We1 + (D+k)*H;
        ai0 += hv*wr[l];  ai1 += hv*wr[l+32];  ai2 += hv*wr[l2];
        aj0 += hv*wr2[l]; aj1 += hv*wr2[l+32]; aj2 += hv*wr2[l2];
    }
    float* yi = g_Yi + row*H;
    float* yj = g_Yj + row*H;
    yi[l]=ai0; yi[l+32]=ai1; if(hi) yi[l2]=ai2;
    yj[l]=aj0; yj[l+32]=aj1; if(hi) yj[l2]=aj2;
}

// ---------------- K1e: BN1 stats, lane-parallel psi + broadcast z loop ----------------
__global__ void k1e_stats(const float* __restrict__ x, const float* __restrict__ We1)
{
    extern __shared__ float sm[];
    float* Yjs = sm;                 // N*H = 9216
    float* xs  = Yjs + N*H;          // 512
    float* w144= xs + N*4;           // 72
    float* w145= w144 + H;           // 72
    float* red = w145 + H;           // 144
    float4* ebuf = (float4*)(red + 2*H);  // 8 warps * 32 recs * float4
    const int tid = threadIdx.x;
    const int b = blockIdx.y;
    {
        const float4* s = (const float4*)(g_Yj + b*N*H);
        float4* d = (float4*)Yjs;
        for (int i=tid;i<N*H/4;i+=256) d[i]=s[i];
        s = (const float4*)(x + b*N*4); d = (float4*)xs;
        for (int i=tid;i<N;i+=256) d[i]=s[i];
    }
    if (tid < H){ w144[tid]=We1[144*H+tid]; w145[tid]=We1[145*H+tid]; }
    for (int i=tid;i<2*H;i+=256) red[i]=0.f;
    __syncthreads();

    const int w = tid>>5, l = tid&31;
    const bool hi = (l<8);
    const int l2 = hi ? l+64 : l;
    const int n = blockIdx.x*8 + w;
    const int row = b*N + n;
    const int deg = g_deg[row];
    const long base = (long)b*E + g_off[row];
    float4* ebw = ebuf + w*32;

    const float yin0 = g_Yi[row*H+l], yin1 = g_Yi[row*H+l+32], yin2 = g_Yi[row*H+l2];
    const float xi0 = xs[n*4+0], xi1 = xs[n*4+1], xi2 = xs[n*4+2], xi3 = xs[n*4+3];
    const float w144l=w144[l], w144m=w144[l+32], w144h=w144[l2];
    const float w145l=w145[l], w145m=w145[l+32], w145h=w145[l2];

    float s0=0.f,s1=0.f,s2=0.f,q0=0.f,q1=0.f,q2=0.f;
    const float4* xsv = (const float4*)xs;

    for (int s=0; s<deg; s+=32){
        const int g = min(32, deg-s);
        // phase 1: lane-parallel psi (lane l owns edge s+l)
        {
            const bool v = (l < g);
            int jt = v ? __ldg(&g_se[base+s+l]).x : n;
            float4 xj = xsv[jt];
            float d0=xi0-xj.x, d1=xi1-xj.y, d2=xi2-xj.z, d3=xi3-xj.w;
            float nrm = psi_f(d0*d0 - d1*d1 - d2*d2 - d3*d3);
            float dts = psi_f(xi0*xj.x - xi1*xj.y - xi2*xj.z - xi3*xj.w);
            if (v) g_nd[base+s+l] = make_float2(nrm, dts);
            ebw[l] = make_float4(__int_as_float(jt), nrm, dts, 0.f);
        }
        __syncwarp();
        // phase 2: z + stats (LDS.128 broadcasts)
        for (int t=0; t<g; t++){
            float4 r = ebw[t];
            int jt = __float_as_int(r.x);
            const float* yj = Yjs + jt*H;
            float z0 = yin0 + yj[l]    + r.y*w144l + r.z*w145l;
            float z1 = yin1 + yj[l+32] + r.y*w144m + r.z*w145m;
            s0+=z0; q0=fmaf(z0,z0,q0); s1+=z1; q1=fmaf(z1,z1,q1);
            if (hi){
                float z2v = yin2 + yj[l2] + r.y*w144h + r.z*w145h;
                s2+=z2v; q2=fmaf(z2v,z2v,q2);
            }
        }
        __syncwarp();
    }
    atomicAdd(&red[l], s0);    atomicAdd(&red[H+l], q0);
    atomicAdd(&red[l+32], s1); atomicAdd(&red[H+l+32], q1);
    if (hi){ atomicAdd(&red[l2], s2); atomicAdd(&red[H+l2], q2); }
    __syncthreads();
    if (tid < 2*H) atomicAdd(&g_stats1[tid], red[tid]);
}

// ---------------- K2: fused edge pipeline, warp-per-node, Yjs in smem ----------------
__global__ void __launch_bounds__(256,2)
k2_edge(const float* __restrict__ x,
        const float* __restrict__ We1,
        const float* __restrict__ g1,  const float* __restrict__ b1,
        const float* __restrict__ We2, const float* __restrict__ be2,
        const float* __restrict__ Wm,  const float* __restrict__ bm,
        const float* __restrict__ Wx1, const float* __restrict__ bx1,
        const float* __restrict__ Wx2,
        float* __restrict__ out)
{
    extern __shared__ float sm[];
    float* Yjs   = sm;                // 9216
    float* xs    = Yjs + N*H;         // 512
    float* We2s  = xs + N*4;          // 5184
    float* Wx1s  = We2s + H*H;        // 5184
    float* Wms   = Wx1s + H*H;        // 72
    float* Wx2s  = Wms + H;           // 72
    float* be2s  = Wx2s + H;          // 72
    float* bx1s  = be2s + H;          // 72
    float* sc1   = bx1s + H;          // 72
    float* sh1   = sc1 + H;           // 72
    float* w144  = sh1 + H;           // 72
    float* w145  = w144 + H;          // 72
    float* stg   = w145 + H;          // 8*H*ZROW = 5760 (shared za/ms staging)

    const int tid = threadIdx.x;
    const int b = blockIdx.y;
    {
        const float4* s = (const float4*)(g_Yj + b*N*H);
        float4* d = (float4*)Yjs;
        for (int i=tid;i<N*H/4;i+=256) d[i]=s[i];
        s = (const float4*)(x + b*N*4); d = (float4*)xs;
        for (int i=tid;i<N;i+=256) d[i]=s[i];
    }
    for (int i=tid;i<H*H;i+=256){ We2s[i]=We2[i]; Wx1s[i]=Wx1[i]; }
    if (tid < H){
        Wms[tid]=Wm[tid]; Wx2s[tid]=Wx2[tid]; be2s[tid]=be2[tid]; bx1s[tid]=bx1[tid];
        // BN1 finalize recomputed per block (cheap, removes a kernel launch)
        const float inv = 1.f/(float)BE;
        float mu  = g_stats1[tid]*inv;
        float var = g_stats1[H+tid]*inv - mu*mu;
        float sc  = g1[tid]*rsqrtf(var+EPS);
        sc1[tid] = sc;
        sh1[tid] = b1[tid] - mu*sc;
        w144[tid]=We1[144*H+tid]; w145[tid]=We1[145*H+tid];
    }
    __syncthreads();

    const int w = tid>>5, l = tid&31;
    const bool hi = (l<8);
    const int l2 = hi ? l+64 : l;
    float* zaw = stg + w*H*ZROW;      // reused for za AND ms (disjoint lifetimes)
    const float bmv = __ldg(bm);

    const int n = blockIdx.x*8 + w;
    const int row = b*N + n;
    const int deg = g_deg[row];
    const long base = (long)b*E + g_off[row];
    float* mout = out + M_OUT_OFF + (size_t)b*E*H;

    const float yin0 = g_Yi[row*H+l], yin1 = g_Yi[row*H+l+32], yin2 = g_Yi[row*H+l2];
    const float xil = (l<4) ? xs[n*4+l] : 0.f;

    float mg0=0.f, mg1=0.f, mg2=0.f;   // magg accumulators (registers)
    float axv=0.f;                      // x-agg accumulator (lanes 0..3)

    for (int s=0; s<deg; s+=8){
        const int g = min(8, deg-s);
        // prefetch next group's uniform loads into L1 (hides L2 latency)
        if (l==0 && s+8 < deg){
            asm volatile("prefetch.global.L1 [%0];" :: "l"(g_se+base+s+8));
            asm volatile("prefetch.global.L1 [%0];" :: "l"(g_nd+base+s+8));
        }
        int jj[8], eid[8]; float nrm[8], dts[8];
        #pragma unroll
        for (int t=0;t<8;t++){
            if (t<g){
                int2 se = __ldg(&g_se[base+s+t]);
                jj[t]=se.x; eid[t]=se.y;
                float2 nd = __ldg(&g_nd[base+s+t]);
                nrm[t]=nd.x; dts[t]=nd.y;
            } else { jj[t]=n; eid[t]=0; nrm[t]=0.f; dts[t]=0.f; }
        }
        // stage z (BN1 + ReLU), pad slots -> 0
        {
            const float w144l=w144[l], w144m=w144[l+32], w144h=w144[l2];
            const float w145l=w145[l], w145m=w145[l+32], w145h=w145[l2];
            const float sc1l=sc1[l], sc1m=sc1[l+32], sc1h=sc1[l2];
            const float sh1l=sh1[l], sh1m=sh1[l+32], sh1h=sh1[l2];
            #pragma unroll
            for (int t=0;t<8;t++){
                const float* yj = Yjs + jj[t]*H;
                float z0 = yin0 + yj[l]    + nrm[t]*w144l + dts[t]*w145l;
                float z1 = yin1 + yj[l+32] + nrm[t]*w144m + dts[t]*w145m;
                zaw[l*ZROW+t]      = (t<g) ? fmaxf(z0*sc1l+sh1l, 0.f) : 0.f;
                zaw[(l+32)*ZROW+t] = (t<g) ? fmaxf(z1*sc1m+sh1m, 0.f) : 0.f;
                if (hi){
                    float z2v = yin2 + yj[l2] + nrm[t]*w144h + dts[t]*w145h;
                    zaw[l2*ZROW+t] = (t<g) ? fmaxf(z2v*sc1h+sh1h, 0.f) : 0.f;
                }
            }
        }
        __syncwarp();
        // GEMM1: relu(za @ We2 + be2)   (f32x2, edge pairs packed)
        ull a0[4], a1[4], a2[4];
        {
            ull be2p0=dup2(be2s[l]), be2p1=dup2(be2s[l+32]), be2p2=dup2(be2s[l2]);
            #pragma unroll
            for (int p=0;p<4;p++){ a0[p]=be2p0; a1[p]=be2p1; a2[p]=be2p2; }
        }
        #pragma unroll 4
        for (int k=0;k<H;k++){
            const ull* zr = (const ull*)(zaw + k*ZROW);
            ull zp0=zr[0], zp1=zr[1], zp2=zr[2], zp3=zr[3];
            ull wd0=dup2(We2s[k*H+l]), wd1=dup2(We2s[k*H+l+32]), wd2=dup2(We2s[k*H+l2]);
            fma2(a0[0],zp0,wd0); fma2(a0[1],zp1,wd0); fma2(a0[2],zp2,wd0); fma2(a0[3],zp3,wd0);
            fma2(a1[0],zp0,wd1); fma2(a1[1],zp1,wd1); fma2(a1[2],zp2,wd1); fma2(a1[3],zp3,wd1);
            fma2(a2[0],zp0,wd2); fma2(a2[1],zp1,wd2); fma2(a2[2],zp2,wd2); fma2(a2[3],zp3,wd2);
        }
        float m0[8], m1[8], m2[8];
        #pragma unroll
        for (int p=0;p<4;p++){
            float2 u0=unpk(a0[p]), u1=unpk(a1[p]), u2=unpk(a2[p]);
            m0[2*p]=fmaxf(u0.x,0.f); m0[2*p+1]=fmaxf(u0.y,0.f);
            m1[2*p]=fmaxf(u1.x,0.f); m1[2*p+1]=fmaxf(u1.y,0.f);
            m2[2*p]=fmaxf(u2.x,0.f); m2[2*p+1]=fmaxf(u2.y,0.f);
        }
        // sigmoid gate: m = mp * sigmoid(mp @ Wm + bm)
        float gs[8];
        {
            const float wm0=Wms[l], wm1=Wms[l+32], wm2=Wms[l2];
            #pragma unroll
            for (int t=0;t<8;t++){
                float p = m0[t]*wm0 + m1[t]*wm1;
                if (hi) p += m2[t]*wm2;
                #pragma unroll
                for (int off=16; off>0; off>>=1) p += __shfl_xor_sync(0xffffffffu, p, off);
                gs[t] = 1.f/(1.f+expf(-(p+bmv)));
            }
        }
        __syncwarp();
        #pragma unroll
        for (int t=0;t<8;t++){
            float v0=m0[t]*gs[t], v1=m1[t]*gs[t], v2=m2[t]*gs[t];
            if (t<g){
                size_t mrow = (size_t)eid[t]*H;
                mout[mrow + l] = v0;
                mout[mrow + l + 32] = v1;
                if (hi) mout[mrow + l2] = v2;
                mg0 += v0; mg1 += v1; mg2 += v2;
            }
            // stage m for GEMM2 (reuse staging buffer)
            zaw[l*ZROW+t]=v0; zaw[(l+32)*ZROW+t]=v1; if(hi) zaw[l2*ZROW+t]=v2;
        }
        __syncwarp();
        // GEMM2: relu(m @ Wx1 + bx1) @ Wx2 -> scalar gate per edge (f32x2)
        ull t0[4], t1[4], t2[4];
        {
            ull bx1p0=dup2(bx1s[l]), bx1p1=dup2(bx1s[l+32]), bx1p2=dup2(bx1s[l2]);
            #pragma unroll
            for (int p=0;p<4;p++){ t0[p]=bx1p0; t1[p]=bx1p1; t2[p]=bx1p2; }
        }
        #pragma unroll 4
        for (int k=0;k<H;k++){
            const ull* zr = (const ull*)(zaw + k*ZROW);
            ull zp0=zr[0], zp1=zr[1], zp2=zr[2], zp3=zr[3];
            ull wd0=dup2(Wx1s[k*H+l]), wd1=dup2(Wx1s[k*H+l+32]), wd2=dup2(Wx1s[k*H+l2]);
            fma2(t0[0],zp0,wd0); fma2(t0[1],zp1,wd0); fma2(t0[2],zp2,wd0); fma2(t0[3],zp3,wd0);
            fma2(t1[0],zp0,wd1); fma2(t1[1],zp1,wd1); fma2(t1[2],zp2,wd1); fma2(t1[3],zp3,wd1);
            fma2(t2[0],zp0,wd2); fma2(t2[1],zp1,wd2); fma2(t2[2],zp2,wd2); fma2(t2[3],zp3,wd2);
        }
        float gate[8];
        {
            const float wx20=Wx2s[l], wx21=Wx2s[l+32], wx22=Wx2s[l2];
            #pragma unroll
            for (int p=0;p<4;p++){
                float2 u0=unpk(t0[p]), u1=unpk(t1[p]), u2=unpk(t2[p]);
                float pa = fmaxf(u0.x,0.f)*wx20 + fmaxf(u1.x,0.f)*wx21;
                float pb = fmaxf(u0.y,0.f)*wx20 + fmaxf(u1.y,0.f)*wx21;
                if (hi){ pa += fmaxf(u2.x,0.f)*wx22; pb += fmaxf(u2.y,0.f)*wx22; }
                gate[2*p]=pa; gate[2*p+1]=pb;
            }
        }
        #pragma unroll
        for (int t=0;t<8;t++){
            float p = gate[t];
            #pragma unroll
            for (int off=16; off>0; off>>=1) p += __shfl_xor_sync(0xffffffffu, p, off);
            gate[t] = p;
        }
        // x aggregation (clipped), register accumulation
        if (l < 4){
            #pragma unroll
            for (int t=0;t<8;t++){
                if (t<g){
                    float xd = xil - xs[jj[t]*4+l];
                    axv += fminf(fmaxf(xd*gate[t], -100.f), 100.f);
                }
            }
        }
    }
    // single plain stores per node — no atomics anywhere
    float* mgrow = g_magg + (size_t)row*H;
    mgrow[l]=mg0; mgrow[l+32]=mg1; if (hi) mgrow[l2]=mg2;
    if (l < 4){
        out[X_OUT_OFF + row*4 + l] = __ldg(&x[row*4+l]) + axv / fmaxf((float)deg, 1.f);
    }
}

// ---------------- K3a: node GEMM (hin @ Wh1 + bh1) + stats2 ----------------
__global__ void k3a_node(const float* __restrict__ h, const float* __restrict__ nattr,
                         const float* __restrict__ Wh1, const float* __restrict__ bh1)
{
    __shared__ float red[2*H];
    __shared__ float mrow_s[8][H];
    const int tid = threadIdx.x;
    const int w = tid>>5, l = tid&31;
    const bool hi = (l<8);
    const int l2 = hi ? l+64 : l;
    for (int i=tid;i<2*H;i+=256) red[i]=0.f;
    __syncthreads();
    const int n = blockIdx.x*8 + w;
    const int b = blockIdx.y;
    const int row = b*N + n;
    const float* mg = g_magg + (size_t)row*H;
    mrow_s[w][l]=mg[l]; mrow_s[w][l+32]=mg[l+32]; if (hi) mrow_s[w][l2]=mg[l2];
    __syncwarp();

    const float* hrow = h + row*D;
    const float* arow = nattr + row*A;
    float a0=bh1[l], a1=bh1[l+32], a2=bh1[l2];
    #pragma unroll 4
    for (int k=0;k<D;k++){
        float v = hrow[k];
        const float* wr = Wh1 + k*H;
        a0 += v*wr[l]; a1 += v*wr[l+32]; a2 += v*wr[l2];
    }
    #pragma unroll 4
    for (int k=0;k<H;k++){
        float v = mrow_s[w][k];
        const float* wr = Wh1 + (D+k)*H;
        a0 += v*wr[l]; a1 += v*wr[l+32]; a2 += v*wr[l2];
    }
    #pragma unroll
    for (int k=0;k<A;k++){
        float v = arow[k];
        const float* wr = Wh1 + (D+H+k)*H;
        a0 += v*wr[l]; a1 += v*wr[l+32]; a2 += v*wr[l2];
    }
    float* z2row = g_z2 + row*H;
    z2row[l]=a0; z2row[l+32]=a1; if (hi) z2row[l2]=a2;
    atomicAdd(&red[l], a0);    atomicAdd(&red[H+l], a0*a0);
    atomicAdd(&red[l+32], a1); atomicAdd(&red[H+l+32], a1*a1);
    if (hi){ atomicAdd(&red[l2], a2); atomicAdd(&red[H+l2], a2*a2); }
    __syncthreads();
    if (tid < 2*H) atomicAdd(&g_stats2[tid], red[tid]);
}

// ---------------- K3c: BN2+ReLU, @Wh2 + bh2, residual -> h_out ----------------
__global__ void k3c_node(const float* __restrict__ h,
                         const float* __restrict__ gh, const float* __restrict__ bh,
                         const float* __restrict__ Wh2,
                         const float* __restrict__ bh2, float* __restrict__ out)
{
    __shared__ float as_[8][H];
    __shared__ float bn2[2*H];
    const int tid=threadIdx.x, w=tid>>5, l=tid&31;
    const bool hi=(l<8);
    const int l2 = hi ? l+64 : l;
    if (tid < H){
        // BN2 finalize recomputed per block
        const float inv = 1.f/(float)BNODES;
        float mu  = g_stats2[tid]*inv;
        float var = g_stats2[H+tid]*inv - mu*mu;
        float sc  = gh[tid]*rsqrtf(var+EPS);
        bn2[tid]   = sc;
        bn2[H+tid] = bh[tid] - mu*sc;
    }
    __syncthreads();
    const int n = blockIdx.x*8 + w;
    const int b = blockIdx.y;
    const int row = b*N + n;
    const float* z2row = g_z2 + row*H;
    as_[w][l]    = fmaxf(z2row[l]   *bn2[l]   +bn2[H+l],    0.f);
    as_[w][l+32] = fmaxf(z2row[l+32]*bn2[l+32]+bn2[H+l+32], 0.f);
    if (hi) as_[w][l2] = fmaxf(z2row[l2]*bn2[l2]+bn2[H+l2], 0.f);
    __syncwarp();
    float a0=bh2[l], a1=bh2[l+32], a2=bh2[l2];
    #pragma unroll 4
    for (int k=0;k<H;k++){
        float v = as_[w][k];
        const float* wr = Wh2 + k*O;
        a0 += v*wr[l]; a1 += v*wr[l+32]; a2 += v*wr[l2];
    }
    const float* hrow = h + row*D;
    out[row*O + l]      = hrow[l]    + a0;
    out[row*O + l + 32] = hrow[l+32] + a1;
    if (hi) out[row*O + l2] = hrow[l2] + a2;
}

// ---------------- host ----------------
extern "C" void kernel_launch(void* const* d_in, const int* in_sizes, int n_in,
                              void* d_out, int out_size) {
    const float* h     = (const float*)d_in[0];
    const float* x     = (const float*)d_in[1];
    const int*   ei    = (const int*)  d_in[2];
    const int*   ej    = (const int*)  d_in[3];
    const float* nattr = (const float*)d_in[4];
    const float* We1   = (const float*)d_in[5];
    const float* g1    = (const float*)d_in[6];
    const float* b1    = (const float*)d_in[7];
    const float* We2   = (const float*)d_in[8];
    const float* be2   = (const float*)d_in[9];
    const float* Wm    = (const float*)d_in[10];
    const float* bm    = (const float*)d_in[11];
    const float* Wx1   = (const float*)d_in[12];
    const float* bx1   = (const float*)d_in[13];
    const float* Wx2   = (const float*)d_in[14];
    const float* Wh1   = (const float*)d_in[15];
    const float* bh1   = (const float*)d_in[16];
    const float* gh    = (const float*)d_in[17];
    const float* bh    = (const float*)d_in[18];
    const float* Wh2   = (const float*)d_in[19];
    const float* bh2   = (const float*)d_in[20];
    float* out = (float*)d_out;

    const int SMEM1 = (N*H + N*4 + 2*H + 2*H + 8*32*4) * sizeof(float);      // 44,160 B
    const int SMEM2 = (N*H + N*4 + 2*H*H + 8*H + 8*H*ZROW) * sizeof(float);  // 105,728 B
    cudaFuncSetAttribute(k1e_stats, cudaFuncAttributeMaxDynamicSharedMemorySize, SMEM1);
    cudaFuncSetAttribute(k2_edge,   cudaFuncAttributeMaxDynamicSharedMemorySize, SMEM2);

    ksort<<<B, 256>>>(ei, ej);                       // launch 1
    k1a_yfac<<<dim3(N/8, B), 256>>>(h, We1);         // launch 2
    k1e_stats<<<dim3(N/8, B), 256, SMEM1>>>(x, We1); // launch 3
    k2_edge<<<dim3(N/8, B), 256, SMEM2>>>(x, We1, g1, b1, We2, be2, Wm, bm,
                                          Wx1, bx1, Wx2, out);  // launch 4 (ncu target)
    k3a_node<<<dim3(N/8, B), 256>>>(h, nattr, Wh1, bh1);        // launch 5
    k3c_node<<<dim3(N/8, B), 256>>>(h, gh, bh, Wh2, bh2, out);  // launch 6
}

// round 6
// speedup vs baseline: 1.1828x; 1.0522x over previous
#include <cuda_runtime.h>
#include <math.h>

#define B  32
#define N  128
#define E  16384
#define D  72
#define H  72
#define O  72
#define A  4
#define EPS 1e-5f
#define BE (B*E)            // 524288
#define BNODES (B*N)        // 4096

#define X_OUT_OFF (B*N*O)                 // 294912
#define M_OUT_OFF (X_OUT_OFF + B*N*4)     // 311296

#define ZROW 12               // staging row stride (floats): 8 edges + 4 pad (16B-aligned rows)
#define SPLIT 4               // edge-segment slices per node (wave-granularity fix)

typedef unsigned long long ull;

// ---------------- device scratch (no allocations allowed) ----------------
__device__ float g_Yi[BNODES*H];     // h @ We1[0:72]
__device__ float g_Yj[BNODES*H];     // h @ We1[72:144]
__device__ float g_maggp[SPLIT*BNODES*H];   // per-slice magg partials
__device__ float g_aggxp[SPLIT*BNODES*4];   // per-slice x-agg partials
__device__ float g_stats1[2*H];
__device__ float g_stats2[2*H];
__device__ float g_z2[BNODES*H];
// CSR sort results
__device__ int    g_off[BNODES];
__device__ int    g_deg[BNODES];
__device__ int2   g_se[BE];          // (ej, original edge id) at sorted position
__device__ float2 g_nd[BE];          // (norms, dots) at sorted position

// ---------------- f32x2 helpers ----------------
__device__ __forceinline__ ull dup2(float w){
    ull r; asm("mov.b64 %0, {%1,%1};" : "=l"(r) : "f"(w)); return r;
}
__device__ __forceinline__ void fma2(ull& c, ull a, ull b){
    asm("fma.rn.f32x2 %0, %1, %2, %0;" : "+l"(c) : "l"(a), "l"(b));
}
__device__ __forceinline__ float2 unpk(ull v){
    float2 r; asm("mov.b64 {%0,%1}, %2;" : "=f"(r.x), "=f"(r.y) : "l"(v)); return r;
}

__device__ __forceinline__ float psi_f(float p){
    return copysignf(log1pf(fabsf(p)), p);
}

// ---------------- KS: counting sort edges by ei (per batch) + zero stats ----------------
__global__ void ksort(const int* __restrict__ ei, const int* __restrict__ ej) {
    __shared__ int cnt[N];
    __shared__ int offs[N];
    __shared__ int curs[N];
    const int b = blockIdx.x;
    const int tid = threadIdx.x;
    if (tid < 2*H){ g_stats1[tid]=0.f; g_stats2[tid]=0.f; }  // racy identical 0-writes: benign
    if (tid < N) cnt[tid] = 0;
    __syncthreads();
    for (int e = tid; e < E; e += 256) atomicAdd(&cnt[ei[b*E+e]], 1);
    __syncthreads();
    if (tid == 0){
        int s = 0;
        for (int n2 = 0; n2 < N; n2++){ offs[n2] = s; s += cnt[n2]; }
    }
    __syncthreads();
    if (tid < N){
        g_off[b*N+tid] = offs[tid];
        g_deg[b*N+tid] = cnt[tid];
        curs[tid] = offs[tid];
    }
    __syncthreads();
    for (int e = tid; e < E; e += 256){
        int n2 = ei[b*E+e];
        int p = atomicAdd(&curs[n2], 1);
        g_se[b*E+p] = make_int2(ej[b*E+e], e);
    }
}

// ---------------- K1a: Y factorization (per-node h @ We1 halves) ----------------
__global__ void k1a_yfac(const float* __restrict__ h, const float* __restrict__ We1) {
    const int tid = threadIdx.x;
    const int w = tid>>5, l = tid&31;
    const bool hi = (l<8);
    const int l2 = hi ? l+64 : l;
    const int n = blockIdx.x*8 + w;
    const int b = blockIdx.y;
    const int row = b*N + n;
    const float* hrow = h + row*D;
    float ai0=0.f, ai1=0.f, ai2=0.f, aj0=0.f, aj1=0.f, aj2=0.f;
    #pragma unroll 4
    for (int k=0;k<D;k++){
        float hv = __ldg(hrow+k);
        const float* wr  = We1 + k*H;
        const float* wr2 = We1 + (D+k)*H;
        ai0 += hv*wr[l];  ai1 += hv*wr[l+32];  ai2 += hv*wr[l2];
        aj0 += hv*wr2[l]; aj1 += hv*wr2[l+32]; aj2 += hv*wr2[l2];
    }
    float* yi = g_Yi + row*H;
    float* yj = g_Yj + row*H;
    yi[l]=ai0; yi[l+32]=ai1; if(hi) yi[l2]=ai2;
    yj[l]=aj0; yj[l+32]=aj1; if(hi) yj[l2]=aj2;
}

// ---------------- K1e: BN1 stats, lane-parallel psi + broadcast z loop ----------------
__global__ void k1e_stats(const float* __restrict__ x, const float* __restrict__ We1)
{
    extern __shared__ float sm[];
    float* Yjs = sm;                 // N*H = 9216
    float* xs  = Yjs + N*H;          // 512
    float* w144= xs + N*4;           // 72
    float* w145= w144 + H;           // 72
    float* red = w145 + H;           // 144
    float4* ebuf = (float4*)(red + 2*H);  // 8 warps * 32 recs * float4
    const int tid = threadIdx.x;
    const int b = blockIdx.y;
    {
        const float4* s = (const float4*)(g_Yj + b*N*H);
        float4* d = (float4*)Yjs;
        for (int i=tid;i<N*H/4;i+=256) d[i]=s[i];
        s = (const float4*)(x + b*N*4); d = (float4*)xs;
        for (int i=tid;i<N;i+=256) d[i]=s[i];
    }
    if (tid < H){ w144[tid]=We1[144*H+tid]; w145[tid]=We1[145*H+tid]; }
    for (int i=tid;i<2*H;i+=256) red[i]=0.f;
    __syncthreads();

    const int w = tid>>5, l = tid&31;
    const bool hi = (l<8);
    const int l2 = hi ? l+64 : l;
    const int n = blockIdx.x*8 + w;
    const int row = b*N + n;
    const int deg = g_deg[row];
    const long base = (long)b*E + g_off[row];
    float4* ebw = ebuf + w*32;

    const float yin0 = g_Yi[row*H+l], yin1 = g_Yi[row*H+l+32], yin2 = g_Yi[row*H+l2];
    const float xi0 = xs[n*4+0], xi1 = xs[n*4+1], xi2 = xs[n*4+2], xi3 = xs[n*4+3];
    const float w144l=w144[l], w144m=w144[l+32], w144h=w144[l2];
    const float w145l=w145[l], w145m=w145[l+32], w145h=w145[l2];

    float s0=0.f,s1=0.f,s2=0.f,q0=0.f,q1=0.f,q2=0.f;
    const float4* xsv = (const float4*)xs;

    for (int s=0; s<deg; s+=32){
        const int g = min(32, deg-s);
        // phase 1: lane-parallel psi (lane l owns edge s+l)
        {
            const bool v = (l < g);
            int jt = v ? __ldg(&g_se[base+s+l]).x : n;
            float4 xj = xsv[jt];
            float d0=xi0-xj.x, d1=xi1-xj.y, d2=xi2-xj.z, d3=xi3-xj.w;
            float nrm = psi_f(d0*d0 - d1*d1 - d2*d2 - d3*d3);
            float dts = psi_f(xi0*xj.x - xi1*xj.y - xi2*xj.z - xi3*xj.w);
            if (v) g_nd[base+s+l] = make_float2(nrm, dts);
            ebw[l] = make_float4(__int_as_float(jt), nrm, dts, 0.f);
        }
        __syncwarp();
        // phase 2: z + stats (LDS.128 broadcasts)
        for (int t=0; t<g; t++){
            float4 r = ebw[t];
            int jt = __float_as_int(r.x);
            const float* yj = Yjs + jt*H;
            float z0 = yin0 + yj[l]    + r.y*w144l + r.z*w145l;
            float z1 = yin1 + yj[l+32] + r.y*w144m + r.z*w145m;
            s0+=z0; q0=fmaf(z0,z0,q0); s1+=z1; q1=fmaf(z1,z1,q1);
            if (hi){
                float z2v = yin2 + yj[l2] + r.y*w144h + r.z*w145h;
                s2+=z2v; q2=fmaf(z2v,z2v,q2);
            }
        }
        __syncwarp();
    }
    atomicAdd(&red[l], s0);    atomicAdd(&red[H+l], q0);
    atomicAdd(&red[l+32], s1); atomicAdd(&red[H+l+32], q1);
    if (hi){ atomicAdd(&red[l2], s2); atomicAdd(&red[H+l2], q2); }
    __syncthreads();
    if (tid < 2*H) atomicAdd(&g_stats1[tid], red[tid]);
}

// ---------------- K2: fused edge pipeline, warp-per-node-slice ----------------
__global__ void __launch_bounds__(256,2)
k2_edge(const float* __restrict__ x,
        const float* __restrict__ We1,
        const float* __restrict__ g1,  const float* __restrict__ b1,
        const float* __restrict__ We2, const float* __restrict__ be2,
        const float* __restrict__ Wm,  const float* __restrict__ bm,
        const float* __restrict__ Wx1, const float* __restrict__ bx1,
        const float* __restrict__ Wx2,
        float* __restrict__ out)
{
    extern __shared__ float sm[];
    float* Yjs   = sm;                // 9216
    float* xs    = Yjs + N*H;         // 512
    float* We2s  = xs + N*4;          // 5184
    float* Wx1s  = We2s + H*H;        // 5184
    float* Wms   = Wx1s + H*H;        // 72
    float* Wx2s  = Wms + H;           // 72
    float* be2s  = Wx2s + H;          // 72
    float* bx1s  = be2s + H;          // 72
    float* sc1   = bx1s + H;          // 72
    float* sh1   = sc1 + H;           // 72
    float* w144  = sh1 + H;           // 72
    float* w145  = w144 + H;          // 72
    float* stg   = w145 + H;          // 8*H*ZROW = 6912 (shared za/ms staging)

    const int tid = threadIdx.x;
    const int b = blockIdx.y;
    const int q = blockIdx.z;         // edge-segment slice
    {
        const float4* s = (const float4*)(g_Yj + b*N*H);
        float4* d = (float4*)Yjs;
        for (int i=tid;i<N*H/4;i+=256) d[i]=s[i];
        s = (const float4*)(x + b*N*4); d = (float4*)xs;
        for (int i=tid;i<N;i+=256) d[i]=s[i];
    }
    for (int i=tid;i<H*H;i+=256){ We2s[i]=We2[i]; Wx1s[i]=Wx1[i]; }
    if (tid < H){
        Wms[tid]=Wm[tid]; Wx2s[tid]=Wx2[tid]; be2s[tid]=be2[tid]; bx1s[tid]=bx1[tid];
        // BN1 finalize recomputed per block (cheap, removes a kernel launch)
        const float inv = 1.f/(float)BE;
        float mu  = g_stats1[tid]*inv;
        float var = g_stats1[H+tid]*inv - mu*mu;
        float sc  = g1[tid]*rsqrtf(var+EPS);
        sc1[tid] = sc;
        sh1[tid] = b1[tid] - mu*sc;
        w144[tid]=We1[144*H+tid]; w145[tid]=We1[145*H+tid];
    }
    __syncthreads();

    const int w = tid>>5, l = tid&31;
    const bool hi = (l<8);
    const int l2 = hi ? l+64 : l;
    float* zaw = stg + w*H*ZROW;      // reused for za AND ms (disjoint lifetimes)
    const float bmv = __ldg(bm);

    const int n = blockIdx.x*8 + w;
    const int row = b*N + n;
    const int deg = g_deg[row];
    const int s0 = (deg*q)/SPLIT;
    const int s1 = (deg*(q+1))/SPLIT;
    const int cntE = s1 - s0;
    const long base = (long)b*E + g_off[row] + s0;
    float* mout = out + M_OUT_OFF + (size_t)b*E*H;

    const float yin0 = g_Yi[row*H+l], yin1 = g_Yi[row*H+l+32], yin2 = g_Yi[row*H+l2];
    const float xil = (l<4) ? xs[n*4+l] : 0.f;

    float mg0=0.f, mg1=0.f, mg2=0.f;   // magg accumulators (registers)
    float axv=0.f;                      // x-agg accumulator (lanes 0..3)

    for (int s=0; s<cntE; s+=8){
        const int g = min(8, cntE-s);
        // prefetch next group's uniform loads into L1 (hides L2 latency)
        if (l==0 && s+8 < cntE){
            asm volatile("prefetch.global.L1 [%0];" :: "l"(g_se+base+s+8));
            asm volatile("prefetch.global.L1 [%0];" :: "l"(g_nd+base+s+8));
        }
        int jj[8], eid[8]; float nrm[8], dts[8];
        #pragma unroll
        for (int t=0;t<8;t++){
            if (t<g){
                int2 se = __ldg(&g_se[base+s+t]);
                jj[t]=se.x; eid[t]=se.y;
                float2 nd = __ldg(&g_nd[base+s+t]);
                nrm[t]=nd.x; dts[t]=nd.y;
            } else { jj[t]=n; eid[t]=0; nrm[t]=0.f; dts[t]=0.f; }
        }
        // stage z (BN1 + ReLU), pad slots -> 0 ; paired STS.64 writes
        {
            const float w144l=w144[l], w144m=w144[l+32], w144h=w144[l2];
            const float w145l=w145[l], w145m=w145[l+32], w145h=w145[l2];
            const float sc1l=sc1[l], sc1m=sc1[l+32], sc1h=sc1[l2];
            const float sh1l=sh1[l], sh1m=sh1[l+32], sh1h=sh1[l2];
            #pragma unroll
            for (int p=0;p<4;p++){
                const int ta=2*p, tb=2*p+1;
                const float* yja = Yjs + jj[ta]*H;
                const float* yjb = Yjs + jj[tb]*H;
                float za0 = yin0 + yja[l]    + nrm[ta]*w144l + dts[ta]*w145l;
                float zb0 = yin0 + yjb[l]    + nrm[tb]*w144l + dts[tb]*w145l;
                float za1 = yin1 + yja[l+32] + nrm[ta]*w144m + dts[ta]*w145m;
                float zb1 = yin1 + yjb[l+32] + nrm[tb]*w144m + dts[tb]*w145m;
                *(float2*)(zaw + l*ZROW + ta) = make_float2(
                    (ta<g) ? fmaxf(za0*sc1l+sh1l, 0.f) : 0.f,
                    (tb<g) ? fmaxf(zb0*sc1l+sh1l, 0.f) : 0.f);
                *(float2*)(zaw + (l+32)*ZROW + ta) = make_float2(
                    (ta<g) ? fmaxf(za1*sc1m+sh1m, 0.f) : 0.f,
                    (tb<g) ? fmaxf(zb1*sc1m+sh1m, 0.f) : 0.f);
                if (hi){
                    float za2 = yin2 + yja[l2] + nrm[ta]*w144h + dts[ta]*w145h;
                    float zb2 = yin2 + yjb[l2] + nrm[tb]*w144h + dts[tb]*w145h;
                    *(float2*)(zaw + l2*ZROW + ta) = make_float2(
                        (ta<g) ? fmaxf(za2*sc1h+sh1h, 0.f) : 0.f,
                        (tb<g) ? fmaxf(zb2*sc1h+sh1h, 0.f) : 0.f);
                }
            }
        }
        __syncwarp();
        // GEMM1: relu(za @ We2 + be2)   (f32x2, edge pairs packed; LDS.128 z reads)
        ull a0[4], a1[4], a2[4];
        {
            ull be2p0=dup2(be2s[l]), be2p1=dup2(be2s[l+32]), be2p2=dup2(be2s[l2]);
            #pragma unroll
            for (int p=0;p<4;p++){ a0[p]=be2p0; a1[p]=be2p1; a2[p]=be2p2; }
        }
        #pragma unroll 4
        for (int k=0;k<H;k++){
            const ulonglong2 u = *(const ulonglong2*)(zaw + k*ZROW);
            const ulonglong2 v = *(const ulonglong2*)(zaw + k*ZROW + 4);
            ull zp0=u.x, zp1=u.y, zp2=v.x, zp3=v.y;
            ull wd0=dup2(We2s[k*H+l]), wd1=dup2(We2s[k*H+l+32]), wd2=dup2(We2s[k*H+l2]);
            fma2(a0[0],zp0,wd0); fma2(a0[1],zp1,wd0); fma2(a0[2],zp2,wd0); fma2(a0[3],zp3,wd0);
            fma2(a1[0],zp0,wd1); fma2(a1[1],zp1,wd1); fma2(a1[2],zp2,wd1); fma2(a1[3],zp3,wd1);
            fma2(a2[0],zp0,wd2); fma2(a2[1],zp1,wd2); fma2(a2[2],zp2,wd2); fma2(a2[3],zp3,wd2);
        }
        float m0[8], m1[8], m2[8];
        #pragma unroll
        for (int p=0;p<4;p++){
            float2 u0=unpk(a0[p]), u1=unpk(a1[p]), u2=unpk(a2[p]);
            m0[2*p]=fmaxf(u0.x,0.f); m0[2*p+1]=fmaxf(u0.y,0.f);
            m1[2*p]=fmaxf(u1.x,0.f); m1[2*p+1]=fmaxf(u1.y,0.f);
            m2[2*p]=fmaxf(u2.x,0.f); m2[2*p+1]=fmaxf(u2.y,0.f);
        }
        // sigmoid gate: m = mp * sigmoid(mp @ Wm + bm)
        float gs[8];
        {
            const float wm0=Wms[l], wm1=Wms[l+32], wm2=Wms[l2];
            #pragma unroll
            for (int t=0;t<8;t++){
                float p = m0[t]*wm0 + m1[t]*wm1;
                if (hi) p += m2[t]*wm2;
                #pragma unroll
                for (int off=16; off>0; off>>=1) p += __shfl_xor_sync(0xffffffffu, p, off);
                gs[t] = 1.f/(1.f+__expf(-(p+bmv)));
            }
        }
        __syncwarp();
        #pragma unroll
        for (int t=0;t<8;t++){
            float v0=m0[t]*gs[t], v1=m1[t]*gs[t], v2=m2[t]*gs[t];
            m0[t]=v0; m1[t]=v1; m2[t]=v2;
            if (t<g){
                size_t mrow = (size_t)eid[t]*H;
                mout[mrow + l] = v0;
                mout[mrow + l + 32] = v1;
                if (hi) mout[mrow + l2] = v2;
                mg0 += v0; mg1 += v1; mg2 += v2;
            }
        }
        // stage m for GEMM2 (reuse staging buffer, paired STS.64)
        #pragma unroll
        for (int p=0;p<4;p++){
            const int ta=2*p;
            *(float2*)(zaw + l*ZROW + ta)      = make_float2(m0[ta], m0[ta+1]);
            *(float2*)(zaw + (l+32)*ZROW + ta) = make_float2(m1[ta], m1[ta+1]);
            if (hi) *(float2*)(zaw + l2*ZROW + ta) = make_float2(m2[ta], m2[ta+1]);
        }
        __syncwarp();
        // GEMM2: relu(m @ Wx1 + bx1) @ Wx2 -> scalar gate per edge (f32x2)
        ull t0[4], t1[4], t2[4];
        {
            ull bx1p0=dup2(bx1s[l]), bx1p1=dup2(bx1s[l+32]), bx1p2=dup2(bx1s[l2]);
            #pragma unroll
            for (int p=0;p<4;p++){ t0[p]=bx1p0; t1[p]=bx1p1; t2[p]=bx1p2; }
        }
        #pragma unroll 4
        for (int k=0;k<H;k++){
            const ulonglong2 u = *(const ulonglong2*)(zaw + k*ZROW);
            const ulonglong2 v = *(const ulonglong2*)(zaw + k*ZROW + 4);
            ull zp0=u.x, zp1=u.y, zp2=v.x, zp3=v.y;
            ull wd0=dup2(Wx1s[k*H+l]), wd1=dup2(Wx1s[k*H+l+32]), wd2=dup2(Wx1s[k*H+l2]);
            fma2(t0[0],zp0,wd0); fma2(t0[1],zp1,wd0); fma2(t0[2],zp2,wd0); fma2(t0[3],zp3,wd0);
            fma2(t1[0],zp0,wd1); fma2(t1[1],zp1,wd1); fma2(t1[2],zp2,wd1); fma2(t1[3],zp3,wd1);
            fma2(t2[0],zp0,wd2); fma2(t2[1],zp1,wd2); fma2(t2[2],zp2,wd2); fma2(t2[3],zp3,wd2);
        }
        float gate[8];
        {
            const float wx20=Wx2s[l], wx21=Wx2s[l+32], wx22=Wx2s[l2];
            #pragma unroll
            for (int p=0;p<4;p++){
                float2 u0=unpk(t0[p]), u1=unpk(t1[p]), u2=unpk(t2[p]);
                float pa = fmaxf(u0.x,0.f)*wx20 + fmaxf(u1.x,0.f)*wx21;
                float pb = fmaxf(u0.y,0.f)*wx20 + fmaxf(u1.y,0.f)*wx21;
                if (hi){ pa += fmaxf(u2.x,0.f)*wx22; pb += fmaxf(u2.y,0.f)*wx22; }
                gate[2*p]=pa; gate[2*p+1]=pb;
            }
        }
        #pragma unroll
        for (int t=0;t<8;t++){
            float p = gate[t];
            #pragma unroll
            for (int off=16; off>0; off>>=1) p += __shfl_xor_sync(0xffffffffu, p, off);
            gate[t] = p;
        }
        // x aggregation (clipped), register accumulation
        if (l < 4){
            #pragma unroll
            for (int t=0;t<8;t++){
                if (t<g){
                    float xd = xil - xs[jj[t]*4+l];
                    axv += fminf(fmaxf(xd*gate[t], -100.f), 100.f);
                }
            }
        }
    }
    // per-slice partial stores — no atomics anywhere
    float* mgrow = g_maggp + ((size_t)q*BNODES + row)*H;
    mgrow[l]=mg0; mgrow[l+32]=mg1; if (hi) mgrow[l2]=mg2;
    if (l < 4){
        g_aggxp[((size_t)q*BNODES + row)*4 + l] = axv;
    }
}

// ---------------- K3a: node GEMM (hin @ Wh1 + bh1) + stats2 + x_out ----------------
__global__ void k3a_node(const float* __restrict__ h, const float* __restrict__ nattr,
                         const float* __restrict__ x,
                         const float* __restrict__ Wh1, const float* __restrict__ bh1,
                         float* __restrict__ out)
{
    __shared__ float red[2*H];
    __shared__ float mrow_s[8][H];
    const int tid = threadIdx.x;
    const int w = tid>>5, l = tid&31;
    const bool hi = (l<8);
    const int l2 = hi ? l+64 : l;
    for (int i=tid;i<2*H;i+=256) red[i]=0.f;
    __syncthreads();
    const int n = blockIdx.x*8 + w;
    const int b = blockIdx.y;
    const int row = b*N + n;
    // sum magg partials over slices
    float m0=0.f, m1=0.f, m2=0.f;
    #pragma unroll
    for (int c=0;c<SPLIT;c++){
        const float* p = g_maggp + ((size_t)c*BNODES + row)*H;
        m0 += p[l]; m1 += p[l+32]; if (hi) m2 += p[l2];
    }
    mrow_s[w][l]=m0; mrow_s[w][l+32]=m1; if (hi) mrow_s[w][l2]=m2;
    __syncwarp();

    const float* hrow = h + row*D;
    const float* arow = nattr + row*A;
    float a0=bh1[l], a1=bh1[l+32], a2=bh1[l2];
    #pragma unroll 4
    for (int k=0;k<D;k++){
        float v = hrow[k];
        const float* wr = Wh1 + k*H;
        a0 += v*wr[l]; a1 += v*wr[l+32]; a2 += v*wr[l2];
    }
    #pragma unroll 4
    for (int k=0;k<H;k++){
        float v = mrow_s[w][k];
        const float* wr = Wh1 + (D+k)*H;
        a0 += v*wr[l]; a1 += v*wr[l+32]; a2 += v*wr[l2];
    }
    #pragma unroll
    for (int k=0;k<A;k++){
        float v = arow[k];
        const float* wr = Wh1 + (D+H+k)*H;
        a0 += v*wr[l]; a1 += v*wr[l+32]; a2 += v*wr[l2];
    }
    float* z2row = g_z2 + row*H;
    z2row[l]=a0; z2row[l+32]=a1; if (hi) z2row[l2]=a2;
    atomicAdd(&red[l], a0);    atomicAdd(&red[H+l], a0*a0);
    atomicAdd(&red[l+32], a1); atomicAdd(&red[H+l+32], a1*a1);
    if (hi){ atomicAdd(&red[l2], a2); atomicAdd(&red[H+l2], a2*a2); }
    __syncthreads();
    if (tid < 2*H) atomicAdd(&g_stats2[tid], red[tid]);
    if (l < 4){
        float ax=0.f;
        #pragma unroll
        for (int c=0;c<SPLIT;c++) ax += g_aggxp[((size_t)c*BNODES + row)*4 + l];
        out[X_OUT_OFF + row*4 + l] = x[row*4 + l] + ax/fmaxf((float)g_deg[row], 1.f);
    }
}

// ---------------- K3c: BN2+ReLU, @Wh2 + bh2, residual -> h_out ----------------
__global__ void k3c_node(const float* __restrict__ h,
                         const float* __restrict__ gh, const float* __restrict__ bh,
                         const float* __restrict__ Wh2,
                         const float* __restrict__ bh2, float* __restrict__ out)
{
    __shared__ float as_[8][H];
    __shared__ float bn2[2*H];
    const int tid=threadIdx.x, w=tid>>5, l=tid&31;
    const bool hi=(l<8);
    const int l2 = hi ? l+64 : l;
    if (tid < H){
        // BN2 finalize recomputed per block
        const float inv = 1.f/(float)BNODES;
        float mu  = g_stats2[tid]*inv;
        float var = g_stats2[H+tid]*inv - mu*mu;
        float sc  = gh[tid]*rsqrtf(var+EPS);
        bn2[tid]   = sc;
        bn2[H+tid] = bh[tid] - mu*sc;
    }
    __syncthreads();
    const int n = blockIdx.x*8 + w;
    const int b = blockIdx.y;
    const int row = b*N + n;
    const float* z2row = g_z2 + row*H;
    as_[w][l]    = fmaxf(z2row[l]   *bn2[l]   +bn2[H+l],    0.f);
    as_[w][l+32] = fmaxf(z2row[l+32]*bn2[l+32]+bn2[H+l+32], 0.f);
    if (hi) as_[w][l2] = fmaxf(z2row[l2]*bn2[l2]+bn2[H+l2], 0.f);
    __syncwarp();
    float a0=bh2[l], a1=bh2[l+32], a2=bh2[l2];
    #pragma unroll 4
    for (int k=0;k<H;k++){
        float v = as_[w][k];
        const float* wr = Wh2 + k*O;
        a0 += v*wr[l]; a1 += v*wr[l+32]; a2 += v*wr[l2];
    }
    const float* hrow = h + row*D;
    out[row*O + l]      = hrow[l]    + a0;
    out[row*O + l + 32] = hrow[l+32] + a1;
    if (hi) out[row*O + l2] = hrow[l2] + a2;
}

// ---------------- host ----------------
extern "C" void kernel_launch(void* const* d_in, const int* in_sizes, int n_in,
                              void* d_out, int out_size) {
    const float* h     = (const float*)d_in[0];
    const float* x     = (const float*)d_in[1];
    const int*   ei    = (const int*)  d_in[2];
    const int*   ej    = (const int*)  d_in[3];
    const float* nattr = (const float*)d_in[4];
    const float* We1   = (const float*)d_in[5];
    const float* g1    = (const float*)d_in[6];
    const float* b1    = (const float*)d_in[7];
    const float* We2   = (const float*)d_in[8];
    const float* be2   = (const float*)d_in[9];
    const float* Wm    = (const float*)d_in[10];
    const float* bm    = (const float*)d_in[11];
    const float* Wx1   = (const float*)d_in[12];
    const float* bx1   = (const float*)d_in[13];
    const float* Wx2   = (const float*)d_in[14];
    const float* Wh1   = (const float*)d_in[15];
    const float* bh1   = (const float*)d_in[16];
    const float* gh    = (const float*)d_in[17];
    const float* bh    = (const float*)d_in[18];
    const float* Wh2   = (const float*)d_in[19];
    const float* bh2   = (const float*)d_in[20];
    float* out = (float*)d_out;

    const int SMEM1 = (N*H + N*4 + 2*H + 2*H + 8*32*4) * sizeof(float);      // 44,160 B
    const int SMEM2 = (N*H + N*4 + 2*H*H + 8*H + 8*H*ZROW) * sizeof(float);  // 111,488 B
    cudaFuncSetAttribute(k1e_stats, cudaFuncAttributeMaxDynamicSharedMemorySize, SMEM1);
    cudaFuncSetAttribute(k2_edge,   cudaFuncAttributeMaxDynamicSharedMemorySize, SMEM2);

    ksort<<<B, 256>>>(ei, ej);                       // launch 1
    k1a_yfac<<<dim3(N/8, B), 256>>>(h, We1);         // launch 2
    k1e_stats<<<dim3(N/8, B), 256, SMEM1>>>(x, We1); // launch 3
    k2_edge<<<dim3(N/8, B, SPLIT), 256, SMEM2>>>(x, We1, g1, b1, We2, be2, Wm, bm,
                                                 Wx1, bx1, Wx2, out);  // launch 4 (ncu target)
    k3a_node<<<dim3(N/8, B), 256>>>(h, nattr, x, Wh1, bh1, out);       // launch 5
    k3c_node<<<dim3(N/8, B), 256>>>(h, gh, bh, Wh2, bh2, out);         // launch 6
}

// round 7
// speedup vs baseline: 1.1907x; 1.0067x over previous
#include <cuda_runtime.h>
#include <math.h>

#define B  32
#define N  128
#define E  16384
#define D  72
#define H  72
#define O  72
#define A  4
#define EPS 1e-5f
#define BE (B*E)            // 524288
#define BNODES (B*N)        // 4096

#define X_OUT_OFF (B*N*O)                 // 294912
#define M_OUT_OFF (X_OUT_OFF + B*N*4)     // 311296

#define ZROW 12               // staging row stride (floats): 8 edges + 4 pad (16B-aligned rows)
#define SPLIT 4               // edge-segment slices per node (wave-granularity fix)

typedef unsigned long long ull;

// ---------------- device scratch (no allocations allowed) ----------------
__device__ float g_Yi[BNODES*H];     // h @ We1[0:72]
__device__ float g_Yj[BNODES*H];     // h @ We1[72:144]
__device__ float g_maggp[SPLIT*BNODES*H];   // per-slice magg partials
__device__ float g_aggxp[SPLIT*BNODES*4];   // per-slice x-agg partials
__device__ float g_stats1[2*H];
__device__ float g_stats2[2*H];
__device__ float g_z2[BNODES*H];
// CSR sort results
__device__ int    g_off[BNODES];
__device__ int    g_deg[BNODES];
__device__ int2   g_se[BE];          // (ej, original edge id) at sorted position
__device__ float2 g_nd[BE];          // (norms, dots) at sorted position

// ---------------- f32x2 helpers ----------------
__device__ __forceinline__ ull dup2(float w){
    ull r; asm("mov.b64 %0, {%1,%1};" : "=l"(r) : "f"(w)); return r;
}
__device__ __forceinline__ void fma2(ull& c, ull a, ull b){
    asm("fma.rn.f32x2 %0, %1, %2, %0;" : "+l"(c) : "l"(a), "l"(b));
}
__device__ __forceinline__ float2 unpk(ull v){
    float2 r; asm("mov.b64 {%0,%1}, %2;" : "=f"(r.x), "=f"(r.y) : "l"(v)); return r;
}

__device__ __forceinline__ float psi_f(float p){
    return copysignf(log1pf(fabsf(p)), p);
}

// ---------------- KS: counting sort edges by ei (per batch) + zero stats ----------------
__global__ void ksort(const int* __restrict__ ei, const int* __restrict__ ej) {
    __shared__ int cnt[N];
    __shared__ int offs[N];
    __shared__ int curs[N];
    const int b = blockIdx.x;
    const int tid = threadIdx.x;
    if (tid < 2*H){ g_stats1[tid]=0.f; g_stats2[tid]=0.f; }  // racy identical 0-writes: benign
    if (tid < N) cnt[tid] = 0;
    __syncthreads();
    for (int e = tid; e < E; e += 256) atomicAdd(&cnt[ei[b*E+e]], 1);
    __syncthreads();
    if (tid == 0){
        int s = 0;
        for (int n2 = 0; n2 < N; n2++){ offs[n2] = s; s += cnt[n2]; }
    }
    __syncthreads();
    if (tid < N){
        g_off[b*N+tid] = offs[tid];
        g_deg[b*N+tid] = cnt[tid];
        curs[tid] = offs[tid];
    }
    __syncthreads();
    for (int e = tid; e < E; e += 256){
        int n2 = ei[b*E+e];
        int p = atomicAdd(&curs[n2], 1);
        g_se[b*E+p] = make_int2(ej[b*E+e], e);
    }
}

// ---------------- K1a: Y factorization (per-node h @ We1 halves) ----------------
__global__ void k1a_yfac(const float* __restrict__ h, const float* __restrict__ We1) {
    const int tid = threadIdx.x;
    const int w = tid>>5, l = tid&31;
    const bool hi = (l<8);
    const int l2 = hi ? l+64 : l;
    const int n = blockIdx.x*8 + w;
    const int b = blockIdx.y;
    const int row = b*N + n;
    const float* hrow = h + row*D;
    float ai0=0.f, ai1=0.f, ai2=0.f, aj0=0.f, aj1=0.f, aj2=0.f;
    #pragma unroll 4
    for (int k=0;k<D;k++){
        float hv = __ldg(hrow+k);
        const float* wr  = We1 + k*H;
        const float* wr2 = We1 + (D+k)*H;
        ai0 += hv*wr[l];  ai1 += hv*wr[l+32];  ai2 += hv*wr[l2];
        aj0 += hv*wr2[l]; aj1 += hv*wr2[l+32]; aj2 += hv*wr2[l2];
    }
    float* yi = g_Yi + row*H;
    float* yj = g_Yj + row*H;
    yi[l]=ai0; yi[l+32]=ai1; if(hi) yi[l2]=ai2;
    yj[l]=aj0; yj[l+32]=aj1; if(hi) yj[l2]=aj2;
}

// ---------------- K1e: BN1 stats, lane-parallel psi + broadcast z loop ----------------
__global__ void k1e_stats(const float* __restrict__ x, const float* __restrict__ We1)
{
    extern __shared__ float sm[];
    float* Yjs = sm;                 // N*H = 9216
    float* xs  = Yjs + N*H;          // 512
    float* w144= xs + N*4;           // 72
    float* w145= w144 + H;           // 72
    float* red = w145 + H;           // 144
    float4* ebuf = (float4*)(red + 2*H);  // 8 warps * 32 recs * float4
    const int tid = threadIdx.x;
    const int b = blockIdx.y;
    {
        const float4* s = (const float4*)(g_Yj + b*N*H);
        float4* d = (float4*)Yjs;
        for (int i=tid;i<N*H/4;i+=256) d[i]=s[i];
        s = (const float4*)(x + b*N*4); d = (float4*)xs;
        for (int i=tid;i<N;i+=256) d[i]=s[i];
    }
    if (tid < H){ w144[tid]=We1[144*H+tid]; w145[tid]=We1[145*H+tid]; }
    for (int i=tid;i<2*H;i+=256) red[i]=0.f;
    __syncthreads();

    const int w = tid>>5, l = tid&31;
    const bool hi = (l<8);
    const int l2 = hi ? l+64 : l;
    const int n = blockIdx.x*8 + w;
    const int row = b*N + n;
    const int deg = g_deg[row];
    const long base = (long)b*E + g_off[row];
    float4* ebw = ebuf + w*32;

    const float yin0 = g_Yi[row*H+l], yin1 = g_Yi[row*H+l+32], yin2 = g_Yi[row*H+l2];
    const float xi0 = xs[n*4+0], xi1 = xs[n*4+1], xi2 = xs[n*4+2], xi3 = xs[n*4+3];
    const float w144l=w144[l], w144m=w144[l+32], w144h=w144[l2];
    const float w145l=w145[l], w145m=w145[l+32], w145h=w145[l2];

    float s0=0.f,s1=0.f,s2=0.f,q0=0.f,q1=0.f,q2=0.f;
    const float4* xsv = (const float4*)xs;

    for (int s=0; s<deg; s+=32){
        const int g = min(32, deg-s);
        // phase 1: lane-parallel psi (lane l owns edge s+l)
        {
            const bool v = (l < g);
            int jt = v ? __ldg(&g_se[base+s+l]).x : n;
            float4 xj = xsv[jt];
            float d0=xi0-xj.x, d1=xi1-xj.y, d2=xi2-xj.z, d3=xi3-xj.w;
            float nrm = psi_f(d0*d0 - d1*d1 - d2*d2 - d3*d3);
            float dts = psi_f(xi0*xj.x - xi1*xj.y - xi2*xj.z - xi3*xj.w);
            if (v) g_nd[base+s+l] = make_float2(nrm, dts);
            ebw[l] = make_float4(__int_as_float(jt), nrm, dts, 0.f);
        }
        __syncwarp();
        // phase 2: z + stats (LDS.128 broadcasts)
        for (int t=0; t<g; t++){
            float4 r = ebw[t];
            int jt = __float_as_int(r.x);
            const float* yj = Yjs + jt*H;
            float z0 = yin0 + yj[l]    + r.y*w144l + r.z*w145l;
            float z1 = yin1 + yj[l+32] + r.y*w144m + r.z*w145m;
            s0+=z0; q0=fmaf(z0,z0,q0); s1+=z1; q1=fmaf(z1,z1,q1);
            if (hi){
                float z2v = yin2 + yj[l2] + r.y*w144h + r.z*w145h;
                s2+=z2v; q2=fmaf(z2v,z2v,q2);
            }
        }
        __syncwarp();
    }
    atomicAdd(&red[l], s0);    atomicAdd(&red[H+l], q0);
    atomicAdd(&red[l+32], s1); atomicAdd(&red[H+l+32], q1);
    if (hi){ atomicAdd(&red[l2], s2); atomicAdd(&red[H+l2], q2); }
    __syncthreads();
    if (tid < 2*H) atomicAdd(&g_stats1[tid], red[tid]);
}

// ---------------- K2: fused edge pipeline, warp-per-node-slice ----------------
__global__ void __launch_bounds__(256,2)
k2_edge(const float* __restrict__ x,
        const float* __restrict__ We1,
        const float* __restrict__ g1,  const float* __restrict__ b1,
        const float* __restrict__ We2, const float* __restrict__ be2,
        const float* __restrict__ Wm,  const float* __restrict__ bm,
        const float* __restrict__ Wx1, const float* __restrict__ bx1,
        const float* __restrict__ Wx2,
        float* __restrict__ out)
{
    extern __shared__ float sm[];
    float* Yjs   = sm;                // 9216
    float* xs    = Yjs + N*H;         // 512
    float* We2s  = xs + N*4;          // 5184
    float* Wx1s  = We2s + H*H;        // 5184
    float* Wms   = Wx1s + H*H;        // 72
    float* Wx2s  = Wms + H;           // 72
    float* be2s  = Wx2s + H;          // 72
    float* bx1s  = be2s + H;          // 72
    float* sc1   = bx1s + H;          // 72
    float* sh1   = sc1 + H;           // 72
    float* w144  = sh1 + H;           // 72
    float* w145  = w144 + H;          // 72
    float* stg   = w145 + H;          // 8*H*ZROW = 6912 (shared za/ms staging)

    const int tid = threadIdx.x;
    const int b = blockIdx.y;
    const int q = blockIdx.z;         // edge-segment slice
    {
        const float4* s = (const float4*)(g_Yj + b*N*H);
        float4* d = (float4*)Yjs;
        for (int i=tid;i<N*H/4;i+=256) d[i]=s[i];
        s = (const float4*)(x + b*N*4); d = (float4*)xs;
        for (int i=tid;i<N;i+=256) d[i]=s[i];
    }
    for (int i=tid;i<H*H;i+=256){ We2s[i]=We2[i]; Wx1s[i]=Wx1[i]; }
    if (tid < H){
        Wms[tid]=Wm[tid]; Wx2s[tid]=Wx2[tid]; be2s[tid]=be2[tid]; bx1s[tid]=bx1[tid];
        // BN1 finalize recomputed per block (cheap, removes a kernel launch)
        const float inv = 1.f/(float)BE;
        float mu  = g_stats1[tid]*inv;
        float var = g_stats1[H+tid]*inv - mu*mu;
        float sc  = g1[tid]*rsqrtf(var+EPS);
        sc1[tid] = sc;
        sh1[tid] = b1[tid] - mu*sc;
        w144[tid]=We1[144*H+tid]; w145[tid]=We1[145*H+tid];
    }
    __syncthreads();

    const int w = tid>>5, l = tid&31;
    const bool hi = (l<8);
    const int l2 = hi ? l+64 : l;
    float* zaw = stg + w*H*ZROW;      // reused for za AND ms (disjoint lifetimes)
    const float bmv = __ldg(bm);

    const int n = blockIdx.x*8 + w;
    const int row = b*N + n;
    const int deg = g_deg[row];
    const int s0 = (deg*q)/SPLIT;
    const int s1 = (deg*(q+1))/SPLIT;
    const int cntE = s1 - s0;
    const long base = (long)b*E + g_off[row] + s0;
    float* mout = out + M_OUT_OFF + (size_t)b*E*H;

    const float yin0 = g_Yi[row*H+l], yin1 = g_Yi[row*H+l+32], yin2 = g_Yi[row*H+l2];
    const float xil = (l<4) ? xs[n*4+l] : 0.f;

    float mg0=0.f, mg1=0.f, mg2=0.f;   // magg accumulators (registers)
    float axv=0.f;                      // x-agg accumulator (lanes 0..3)

    for (int s=0; s<cntE; s+=8){
        const int g = min(8, cntE-s);
        // prefetch next group's uniform loads into L1 (hides L2 latency)
        if (l==0 && s+8 < cntE){
            asm volatile("prefetch.global.L1 [%0];" :: "l"(g_se+base+s+8));
            asm volatile("prefetch.global.L1 [%0];" :: "l"(g_nd+base+s+8));
        }
        int jj[8], eid[8]; float nrm[8], dts[8];
        #pragma unroll
        for (int t=0;t<8;t++){
            if (t<g){
                int2 se = __ldg(&g_se[base+s+t]);
                jj[t]=se.x; eid[t]=se.y;
                float2 nd = __ldg(&g_nd[base+s+t]);
                nrm[t]=nd.x; dts[t]=nd.y;
            } else { jj[t]=n; eid[t]=0; nrm[t]=0.f; dts[t]=0.f; }
        }
        // stage z (BN1 + ReLU), pad slots -> 0 ; paired STS.64 writes
        {
            const float w144l=w144[l], w144m=w144[l+32], w144h=w144[l2];
            const float w145l=w145[l], w145m=w145[l+32], w145h=w145[l2];
            const float sc1l=sc1[l], sc1m=sc1[l+32], sc1h=sc1[l2];
            const float sh1l=sh1[l], sh1m=sh1[l+32], sh1h=sh1[l2];
            #pragma unroll
            for (int p=0;p<4;p++){
                const int ta=2*p, tb=2*p+1;
                const float* yja = Yjs + jj[ta]*H;
                const float* yjb = Yjs + jj[tb]*H;
                float za0 = yin0 + yja[l]    + nrm[ta]*w144l + dts[ta]*w145l;
                float zb0 = yin0 + yjb[l]    + nrm[tb]*w144l + dts[tb]*w145l;
                float za1 = yin1 + yja[l+32] + nrm[ta]*w144m + dts[ta]*w145m;
                float zb1 = yin1 + yjb[l+32] + nrm[tb]*w144m + dts[tb]*w145m;
                *(float2*)(zaw + l*ZROW + ta) = make_float2(
                    (ta<g) ? fmaxf(za0*sc1l+sh1l, 0.f) : 0.f,
                    (tb<g) ? fmaxf(zb0*sc1l+sh1l, 0.f) : 0.f);
                *(float2*)(zaw + (l+32)*ZROW + ta) = make_float2(
                    (ta<g) ? fmaxf(za1*sc1m+sh1m, 0.f) : 0.f,
                    (tb<g) ? fmaxf(zb1*sc1m+sh1m, 0.f) : 0.f);
                if (hi){
                    float za2 = yin2 + yja[l2] + nrm[ta]*w144h + dts[ta]*w145h;
                    float zb2 = yin2 + yjb[l2] + nrm[tb]*w144h + dts[tb]*w145h;
                    *(float2*)(zaw + l2*ZROW + ta) = make_float2(
                        (ta<g) ? fmaxf(za2*sc1h+sh1h, 0.f) : 0.f,
                        (tb<g) ? fmaxf(zb2*sc1h+sh1h, 0.f) : 0.f);
                }
            }
        }
        __syncwarp();
        // GEMM1: relu(za @ We2 + be2)   (f32x2, edge pairs packed; LDS.128 z reads)
        ull a0[4], a1[4], a2[4];
        {
            ull be2p0=dup2(be2s[l]), be2p1=dup2(be2s[l+32]), be2p2=dup2(be2s[l2]);
            #pragma unroll
            for (int p=0;p<4;p++){ a0[p]=be2p0; a1[p]=be2p1; a2[p]=be2p2; }
        }
        #pragma unroll 4
        for (int k=0;k<H;k++){
            const ulonglong2 u = *(const ulonglong2*)(zaw + k*ZROW);
            const ulonglong2 v = *(const ulonglong2*)(zaw + k*ZROW + 4);
            ull zp0=u.x, zp1=u.y, zp2=v.x, zp3=v.y;
            ull wd0=dup2(We2s[k*H+l]), wd1=dup2(We2s[k*H+l+32]), wd2=dup2(We2s[k*H+l2]);
            fma2(a0[0],zp0,wd0); fma2(a0[1],zp1,wd0); fma2(a0[2],zp2,wd0); fma2(a0[3],zp3,wd0);
            fma2(a1[0],zp0,wd1); fma2(a1[1],zp1,wd1); fma2(a1[2],zp2,wd1); fma2(a1[3],zp3,wd1);
            fma2(a2[0],zp0,wd2); fma2(a2[1],zp1,wd2); fma2(a2[2],zp2,wd2); fma2(a2[3],zp3,wd2);
        }
        float m0[8], m1[8], m2[8];
        #pragma unroll
        for (int p=0;p<4;p++){
            float2 u0=unpk(a0[p]), u1=unpk(a1[p]), u2=unpk(a2[p]);
            m0[2*p]=fmaxf(u0.x,0.f); m0[2*p+1]=fmaxf(u0.y,0.f);
            m1[2*p]=fmaxf(u1.x,0.f); m1[2*p+1]=fmaxf(u1.y,0.f);
            m2[2*p]=fmaxf(u2.x,0.f); m2[2*p+1]=fmaxf(u2.y,0.f);
        }
        // sigmoid gate: m = mp * sigmoid(mp @ Wm + bm)
        float gs[8];
        {
            const float wm0=Wms[l], wm1=Wms[l+32], wm2=Wms[l2];
            #pragma unroll
            for (int t=0;t<8;t++){
                float p = m0[t]*wm0 + m1[t]*wm1;
                if (hi) p += m2[t]*wm2;
                #pragma unroll
                for (int off=16; off>0; off>>=1) p += __shfl_xor_sync(0xffffffffu, p, off);
                gs[t] = 1.f/(1.f+__expf(-(p+bmv)));
            }
        }
        __syncwarp();
        #pragma unroll
        for (int t=0;t<8;t++){
            float v0=m0[t]*gs[t], v1=m1[t]*gs[t], v2=m2[t]*gs[t];
            m0[t]=v0; m1[t]=v1; m2[t]=v2;
            if (t<g){
                size_t mrow = (size_t)eid[t]*H;
                mout[mrow + l] = v0;
                mout[mrow + l + 32] = v1;
                if (hi) mout[mrow + l2] = v2;
                mg0 += v0; mg1 += v1; mg2 += v2;
            }
        }
        // stage m for GEMM2 (reuse staging buffer, paired STS.64)
        #pragma unroll
        for (int p=0;p<4;p++){
            const int ta=2*p;
            *(float2*)(zaw + l*ZROW + ta)      = make_float2(m0[ta], m0[ta+1]);
            *(float2*)(zaw + (l+32)*ZROW + ta) = make_float2(m1[ta], m1[ta+1]);
            if (hi) *(float2*)(zaw + l2*ZROW + ta) = make_float2(m2[ta], m2[ta+1]);
        }
        __syncwarp();
        // GEMM2: relu(m @ Wx1 + bx1) @ Wx2 -> scalar gate per edge (f32x2)
        ull t0[4], t1[4], t2[4];
        {
            ull bx1p0=dup2(bx1s[l]), bx1p1=dup2(bx1s[l+32]), bx1p2=dup2(bx1s[l2]);
            #pragma unroll
            for (int p=0;p<4;p++){ t0[p]=bx1p0; t1[p]=bx1p1; t2[p]=bx1p2; }
        }
        #pragma unroll 4
        for (int k=0;k<H;k++){
            const ulonglong2 u = *(const ulonglong2*)(zaw + k*ZROW);
            const ulonglong2 v = *(const ulonglong2*)(zaw + k*ZROW + 4);
            ull zp0=u.x, zp1=u.y, zp2=v.x, zp3=v.y;
            ull wd0=dup2(Wx1s[k*H+l]), wd1=dup2(Wx1s[k*H+l+32]), wd2=dup2(Wx1s[k*H+l2]);
            fma2(t0[0],zp0,wd0); fma2(t0[1],zp1,wd0); fma2(t0[2],zp2,wd0); fma2(t0[3],zp3,wd0);
            fma2(t1[0],zp0,wd1); fma2(t1[1],zp1,wd1); fma2(t1[2],zp2,wd1); fma2(t1[3],zp3,wd1);
            fma2(t2[0],zp0,wd2); fma2(t2[1],zp1,wd2); fma2(t2[2],zp2,wd2); fma2(t2[3],zp3,wd2);
        }
        float gate[8];
        {
            const float wx20=Wx2s[l], wx21=Wx2s[l+32], wx22=Wx2s[l2];
            #pragma unroll
            for (int p=0;p<4;p++){
                float2 u0=unpk(t0[p]), u1=unpk(t1[p]), u2=unpk(t2[p]);
                float pa = fmaxf(u0.x,0.f)*wx20 + fmaxf(u1.x,0.f)*wx21;
                float pb = fmaxf(u0.y,0.f)*wx20 + fmaxf(u1.y,0.f)*wx21;
                if (hi){ pa += fmaxf(u2.x,0.f)*wx22; pb += fmaxf(u2.y,0.f)*wx22; }
                gate[2*p]=pa; gate[2*p+1]=pb;
            }
        }
        #pragma unroll
        for (int t=0;t<8;t++){
            float p = gate[t];
            #pragma unroll
            for (int off=16; off>0; off>>=1) p += __shfl_xor_sync(0xffffffffu, p, off);
            gate[t] = p;
        }
        // x aggregation (clipped), register accumulation
        if (l < 4){
            #pragma unroll
            for (int t=0;t<8;t++){
                if (t<g){
                    float xd = xil - xs[jj[t]*4+l];
                    axv += fminf(fmaxf(xd*gate[t], -100.f), 100.f);
                }
            }
        }
    }
    // per-slice partial stores — no atomics anywhere
    float* mgrow = g_maggp + ((size_t)q*BNODES + row)*H;
    mgrow[l]=mg0; mgrow[l+32]=mg1; if (hi) mgrow[l2]=mg2;
    if (l < 4){
        g_aggxp[((size_t)q*BNODES + row)*4 + l] = axv;
    }
}

// ---------------- K3a: node GEMM (hin @ Wh1 + bh1) + stats2 + x_out ----------------
__global__ void k3a_node(const float* __restrict__ h, const float* __restrict__ nattr,
                         const float* __restrict__ x,
                         const float* __restrict__ Wh1, const float* __restrict__ bh1,
                         float* __restrict__ out)
{
    __shared__ float red[2*H];
    __shared__ float mrow_s[8][H];
    const int tid = threadIdx.x;
    const int w = tid>>5, l = tid&31;
    const bool hi = (l<8);
    const int l2 = hi ? l+64 : l;
    for (int i=tid;i<2*H;i+=256) red[i]=0.f;
    __syncthreads();
    const int n = blockIdx.x*8 + w;
    const int b = blockIdx.y;
    const int row = b*N + n;
    // sum magg partials over slices
    float m0=0.f, m1=0.f, m2=0.f;
    #pragma unroll
    for (int c=0;c<SPLIT;c++){
        const float* p = g_maggp + ((size_t)c*BNODES + row)*H;
        m0 += p[l]; m1 += p[l+32]; if (hi) m2 += p[l2];
    }
    mrow_s[w][l]=m0; mrow_s[w][l+32]=m1; if (hi) mrow_s[w][l2]=m2;
    __syncwarp();

    const float* hrow = h + row*D;
    const float* arow = nattr + row*A;
    float a0=bh1[l], a1=bh1[l+32], a2=bh1[l2];
    #pragma unroll 4
    for (int k=0;k<D;k++){
        float v = hrow[k];
        const float* wr = Wh1 + k*H;
        a0 += v*wr[l]; a1 += v*wr[l+32]; a2 += v*wr[l2];
    }
    #pragma unroll 4
    for (int k=0;k<H;k++){
        float v = mrow_s[w][k];
        const float* wr = Wh1 + (D+k)*H;
        a0 += v*wr[l]; a1 += v*wr[l+32]; a2 += v*wr[l2];
    }
    #pragma unroll
    for (int k=0;k<A;k++){
        float v = arow[k];
        const float* wr = Wh1 + (D+H+k)*H;
        a0 += v*wr[l]; a1 += v*wr[l+32]; a2 += v*wr[l2];
    }
    float* z2row = g_z2 + row*H;
    z2row[l]=a0; z2row[l+32]=a1; if (hi) z2row[l2]=a2;
    atomicAdd(&red[l], a0);    atomicAdd(&red[H+l], a0*a0);
    atomicAdd(&red[l+32], a1); atomicAdd(&red[H+l+32], a1*a1);
    if (hi){ atomicAdd(&red[l2], a2); atomicAdd(&red[H+l2], a2*a2); }
    __syncthreads();
    if (tid < 2*H) atomicAdd(&g_stats2[tid], red[tid]);
    if (l < 4){
        float ax=0.f;
        #pragma unroll
        for (int c=0;c<SPLIT;c++) ax += g_aggxp[((size_t)c*BNODES + row)*4 + l];
        out[X_OUT_OFF + row*4 + l] = x[row*4 + l] + ax/fmaxf((float)g_deg[row], 1.f);
    }
}

// ---------------- K3c: BN2+ReLU, @Wh2 + bh2, residual -> h_out ----------------
__global__ void k3c_node(const float* __restrict__ h,
                         const float* __restrict__ gh, const float* __restrict__ bh,
                         const float* __restrict__ Wh2,
                         const float* __restrict__ bh2, float* __restrict__ out)
{
    __shared__ float as_[8][H];
    __shared__ float bn2[2*H];
    const int tid=threadIdx.x, w=tid>>5, l=tid&31;
    const bool hi=(l<8);
    const int l2 = hi ? l+64 : l;
    if (tid < H){
        // BN2 finalize recomputed per block
        const float inv = 1.f/(float)BNODES;
        float mu  = g_stats2[tid]*inv;
        float var = g_stats2[H+tid]*inv - mu*mu;
        float sc  = gh[tid]*rsqrtf(var+EPS);
        bn2[tid]   = sc;
        bn2[H+tid] = bh[tid] - mu*sc;
    }
    __syncthreads();
    const int n = blockIdx.x*8 + w;
    const int b = blockIdx.y;
    const int row = b*N + n;
    const float* z2row = g_z2 + row*H;
    as_[w][l]    = fmaxf(z2row[l]   *bn2[l]   +bn2[H+l],    0.f);
    as_[w][l+32] = fmaxf(z2row[l+32]*bn2[l+32]+bn2[H+l+32], 0.f);
    if (hi) as_[w][l2] = fmaxf(z2row[l2]*bn2[l2]+bn2[H+l2], 0.f);
    __syncwarp();
    float a0=bh2[l], a1=bh2[l+32], a2=bh2[l2];
    #pragma unroll 4
    for (int k=0;k<H;k++){
        float v = as_[w][k];
        const float* wr = Wh2 + k*O;
        a0 += v*wr[l]; a1 += v*wr[l+32]; a2 += v*wr[l2];
    }
    const float* hrow = h + row*D;
    out[row*O + l]      = hrow[l]    + a0;
    out[row*O + l + 32] = hrow[l+32] + a1;
    if (hi) out[row*O + l2] = hrow[l2] + a2;
}

// ---------------- host ----------------
extern "C" void kernel_launch(void* const* d_in, const int* in_sizes, int n_in,
                              void* d_out, int out_size) {
    const float* h     = (const float*)d_in[0];
    const float* x     = (const float*)d_in[1];
    const int*   ei    = (const int*)  d_in[2];
    const int*   ej    = (const int*)  d_in[3];
    const float* nattr = (const float*)d_in[4];
    const float* We1   = (const float*)d_in[5];
    const float* g1    = (const float*)d_in[6];
    const float* b1    = (const float*)d_in[7];
    const float* We2   = (const float*)d_in[8];
    const float* be2   = (const float*)d_in[9];
    const float* Wm    = (const float*)d_in[10];
    const float* bm    = (const float*)d_in[11];
    const float* Wx1   = (const float*)d_in[12];
    const float* bx1   = (const float*)d_in[13];
    const float* Wx2   = (const float*)d_in[14];
    const float* Wh1   = (const float*)d_in[15];
    const float* bh1   = (const float*)d_in[16];
    const float* gh    = (const float*)d_in[17];
    const float* bh    = (const float*)d_in[18];
    const float* Wh2   = (const float*)d_in[19];
    const float* bh2   = (const float*)d_in[20];
    float* out = (float*)d_out;

    const int SMEM1 = (N*H + N*4 + 2*H + 2*H + 8*32*4) * sizeof(float);      // 44,160 B
    const int SMEM2 = (N*H + N*4 + 2*H*H + 8*H + 8*H*ZROW) * sizeof(float);  // 111,488 B
    cudaFuncSetAttribute(k1e_stats, cudaFuncAttributeMaxDynamicSharedMemorySize, SMEM1);
    cudaFuncSetAttribute(k2_edge,   cudaFuncAttributeMaxDynamicSharedMemorySize, SMEM2);

    ksort<<<B, 256>>>(ei, ej);                       // launch 1
    k1a_yfac<<<dim3(N/8, B), 256>>>(h, We1);         // launch 2
    k1e_stats<<<dim3(N/8, B), 256, SMEM1>>>(x, We1); // launch 3
    k2_edge<<<dim3(N/8, B, SPLIT), 256, SMEM2>>>(x, We1, g1, b1, We2, be2, Wm, bm,
                                                 Wx1, bx1, Wx2, out);  // launch 4 (ncu target)
    k3a_node<<<dim3(N/8, B), 256>>>(h, nattr, x, Wh1, bh1, out);       // launch 5
    k3c_node<<<dim3(N/8, B), 256>>>(h, gh, bh, Wh2, bh2, out);         // launch 6
}